// round 4
// baseline (speedup 1.0000x reference)
#include <cuda_runtime.h>
#include <cuda_bf16.h>
#include <math.h>

// Shapes (fixed for this problem)
#define BB 2
#define TT 2048
#define DD 1024
#define HH 16
#define DH 64
#define MM (BB*TT)   // 4096

// Scratch (no cudaMalloc allowed)
__device__ float g_WeffQ[DD*DD];   // [j][d], j = h*64+e
__device__ float g_WeffK[DD*DD];
__device__ float g_Qp[MM*DD];      // (B*T, D) row-major, col j = h*64+e
__device__ float g_Kp[MM*DD];
__device__ float g_V [MM*DD];
__device__ float g_O [MM*DD];

// ---------------------------------------------------------------------------
// Weff fold: WeffT[h*64+e][d] = sum_c W[h*64+c][d] * S[h][c][e]
// grid (D/256, H, 2), 256 threads; z=0 -> (Wq,Sq,WeffQ), z=1 -> (Wk,Sk,WeffK)
// ---------------------------------------------------------------------------
__global__ __launch_bounds__(256)
void weff_kernel(const float* __restrict__ Wq, const float* __restrict__ Wk,
                 const float* __restrict__ Sq, const float* __restrict__ Sk)
{
    const int h = blockIdx.y;
    const bool isK = (blockIdx.z != 0);
    const float* __restrict__ W = isK ? Wk : Wq;
    const float* __restrict__ S = isK ? Sk : Sq;
    float* __restrict__ outp = isK ? g_WeffK : g_WeffQ;

    __shared__ float s_s[DH*DH];    // S[h][c][e]
    for (int i = threadIdx.x; i < DH*DH; i += 256)
        s_s[i] = S[h*DH*DH + i];
    __syncthreads();

    const int d = blockIdx.x * 256 + threadIdx.x;
    float acc[DH];
#pragma unroll
    for (int e = 0; e < DH; e++) acc[e] = 0.f;

    for (int c = 0; c < DH; c++) {
        const float w = W[(h*DH + c)*DD + d];   // coalesced across threads
#pragma unroll
        for (int e = 0; e < DH; e++)
            acc[e] += w * s_s[c*DH + e];        // broadcast
    }
#pragma unroll
    for (int e = 0; e < DH; e++)
        outp[(h*DH + e)*DD + d] = acc[e];
}

// ---------------------------------------------------------------------------
// NT SGEMM: C[m][n] = sum_k A[m][k] * Bt[n][k]
// M=4096, N=1024, K=1024 fixed. BM=BN=128, BK=16, 256 threads, 8x8 per thread.
// grid (N/128=8, M/128=32)
// ---------------------------------------------------------------------------
__global__ __launch_bounds__(256)
void gemm_nt_kernel(const float* __restrict__ A, const float* __restrict__ Bt,
                    float* __restrict__ C)
{
    const int K = DD;
    __shared__ float As[16][128];
    __shared__ float Bs[16][128];

    const int tid = threadIdx.x;
    const int tx = tid & 15;         // 0..15  (n direction)
    const int ty = tid >> 4;         // 0..15  (m direction)
    const int m0 = blockIdx.y * 128;
    const int n0 = blockIdx.x * 128;

    // loader mapping: each thread loads 2 float4 per tile
    const int lr = tid >> 2;         // 0..63 row group
    const int lc = (tid & 3) * 4;    // k offset 0,4,8,12

    float acc[8][8];
#pragma unroll
    for (int i = 0; i < 8; i++)
#pragma unroll
        for (int j = 0; j < 8; j++) acc[i][j] = 0.f;

    for (int k0 = 0; k0 < K; k0 += 16) {
        __syncthreads();
        // A tile rows lr and lr+64
        {
            float4 a0 = *(const float4*)(A + (size_t)(m0 + lr     )*K + k0 + lc);
            float4 a1 = *(const float4*)(A + (size_t)(m0 + lr + 64)*K + k0 + lc);
            As[lc+0][lr] = a0.x; As[lc+1][lr] = a0.y; As[lc+2][lr] = a0.z; As[lc+3][lr] = a0.w;
            As[lc+0][lr+64] = a1.x; As[lc+1][lr+64] = a1.y; As[lc+2][lr+64] = a1.z; As[lc+3][lr+64] = a1.w;
            float4 b0 = *(const float4*)(Bt + (size_t)(n0 + lr     )*K + k0 + lc);
            float4 b1 = *(const float4*)(Bt + (size_t)(n0 + lr + 64)*K + k0 + lc);
            Bs[lc+0][lr] = b0.x; Bs[lc+1][lr] = b0.y; Bs[lc+2][lr] = b0.z; Bs[lc+3][lr] = b0.w;
            Bs[lc+0][lr+64] = b1.x; Bs[lc+1][lr+64] = b1.y; Bs[lc+2][lr+64] = b1.z; Bs[lc+3][lr+64] = b1.w;
        }
        __syncthreads();

#pragma unroll
        for (int kk = 0; kk < 16; kk++) {
            float ra[8], rb[8];
            float4 a0 = *(const float4*)&As[kk][ty*8];
            float4 a1 = *(const float4*)&As[kk][ty*8 + 4];
            ra[0]=a0.x; ra[1]=a0.y; ra[2]=a0.z; ra[3]=a0.w;
            ra[4]=a1.x; ra[5]=a1.y; ra[6]=a1.z; ra[7]=a1.w;
            float4 b0 = *(const float4*)&Bs[kk][tx*8];
            float4 b1 = *(const float4*)&Bs[kk][tx*8 + 4];
            rb[0]=b0.x; rb[1]=b0.y; rb[2]=b0.z; rb[3]=b0.w;
            rb[4]=b1.x; rb[5]=b1.y; rb[6]=b1.z; rb[7]=b1.w;
#pragma unroll
            for (int i = 0; i < 8; i++)
#pragma unroll
                for (int j = 0; j < 8; j++)
                    acc[i][j] += ra[i] * rb[j];
        }
    }

#pragma unroll
    for (int i = 0; i < 8; i++) {
        float* crow = C + (size_t)(m0 + ty*8 + i)*DD + n0 + tx*8;
        float4 v0 = make_float4(acc[i][0], acc[i][1], acc[i][2], acc[i][3]);
        float4 v1 = make_float4(acc[i][4], acc[i][5], acc[i][6], acc[i][7]);
        *(float4*)(crow)     = v0;
        *(float4*)(crow + 4) = v1;
    }
}

// ---------------------------------------------------------------------------
// Flash attention (fp32): 1 thread per query row, 128 rows per block.
// grid (T/128=16, B*H=32), 128 threads. K/V tiles of 64 keys in SMEM.
// mask is all-true in this problem -> omitted.
// ---------------------------------------------------------------------------
__global__ __launch_bounds__(128)
void attn_kernel()
{
    const int bh = blockIdx.y;
    const int b = bh >> 4;
    const int h = bh & 15;
    const int r = blockIdx.x * 128 + threadIdx.x;   // query row within T

    __shared__ float4 Ks4[64*16];   // 64 keys x 64 floats
    __shared__ float4 Vs4[64*16];

    const float* __restrict__ qptr = g_Qp + ((size_t)(b*TT + r) << 10) + (h << 6);
    const float* __restrict__ Kb   = g_Kp + (((size_t)b*TT) << 10) + (h << 6);
    const float* __restrict__ Vb   = g_V  + (((size_t)b*TT) << 10) + (h << 6);

    float4 qv[16];
#pragma unroll
    for (int d4 = 0; d4 < 16; d4++) qv[d4] = ((const float4*)qptr)[d4];

    float4 ov[16];
#pragma unroll
    for (int d4 = 0; d4 < 16; d4++) ov[d4] = make_float4(0.f, 0.f, 0.f, 0.f);

    float m = -INFINITY, l = 0.f;
    const float scale = 0.125f;    // DH^-0.5

    for (int s0 = 0; s0 < TT; s0 += 64) {
        __syncthreads();
#pragma unroll
        for (int i = 0; i < 8; i++) {
            const int fi  = threadIdx.x + (i << 7);   // 0..1023
            const int row = fi >> 4;
            const int c4  = fi & 15;
            Ks4[fi] = ((const float4*)(Kb + ((size_t)(s0 + row) << 10)))[c4];
            Vs4[fi] = ((const float4*)(Vb + ((size_t)(s0 + row) << 10)))[c4];
        }
        __syncthreads();

#pragma unroll
        for (int g = 0; g < 4; g++) {
            float sc[16];
#pragma unroll
            for (int jj = 0; jj < 16; jj++) {
                const int j = g*16 + jj;
                float a0 = 0.f, a1 = 0.f, a2 = 0.f, a3 = 0.f;
#pragma unroll
                for (int d4 = 0; d4 < 16; d4++) {
                    float4 k4 = Ks4[j*16 + d4];
                    float4 q4 = qv[d4];
                    a0 += q4.x * k4.x;
                    a1 += q4.y * k4.y;
                    a2 += q4.z * k4.z;
                    a3 += q4.w * k4.w;
                }
                sc[jj] = ((a0 + a1) + (a2 + a3)) * scale;
            }
            float gm = sc[0];
#pragma unroll
            for (int jj = 1; jj < 16; jj++) gm = fmaxf(gm, sc[jj]);
            const float m_new = fmaxf(m, gm);
            const float corr = __expf(m - m_new);
            float psum = 0.f;
#pragma unroll
            for (int jj = 0; jj < 16; jj++) {
                sc[jj] = __expf(sc[jj] - m_new);
                psum += sc[jj];
            }
            l = l * corr + psum;
            m = m_new;
#pragma unroll
            for (int d4 = 0; d4 < 16; d4++) {
                ov[d4].x *= corr; ov[d4].y *= corr; ov[d4].z *= corr; ov[d4].w *= corr;
            }
#pragma unroll
            for (int jj = 0; jj < 16; jj++) {
                const float p = sc[jj];
                const int base = (g*16 + jj) * 16;
#pragma unroll
                for (int d4 = 0; d4 < 16; d4++) {
                    float4 v4 = Vs4[base + d4];
                    ov[d4].x += p * v4.x;
                    ov[d4].y += p * v4.y;
                    ov[d4].z += p * v4.z;
                    ov[d4].w += p * v4.w;
                }
            }
        }
    }

    const float inv = 1.0f / l;
    float* optr = g_O + ((size_t)(b*TT + r) << 10) + (h << 6);
#pragma unroll
    for (int d4 = 0; d4 < 16; d4++) {
        float4 o = ov[d4];
        o.x *= inv; o.y *= inv; o.z *= inv; o.w *= inv;
        ((float4*)optr)[d4] = o;
    }
}

// ---------------------------------------------------------------------------
// Launch. Inputs: 0=x, 1=mask, 2=Wq, 3=Wk, 4=Wv, 5=Wo, 6=S_q, 7=S_k
// ---------------------------------------------------------------------------
extern "C" void kernel_launch(void* const* d_in, const int* in_sizes, int n_in,
                              void* d_out, int out_size)
{
    const float* x  = (const float*)d_in[0];
    const float* Wq = (const float*)d_in[2];
    const float* Wk = (const float*)d_in[3];
    const float* Wv = (const float*)d_in[4];
    const float* Wo = (const float*)d_in[5];
    const float* Sq = (const float*)d_in[6];
    const float* Sk = (const float*)d_in[7];
    float* outp = (float*)d_out;

    float *dWeffQ, *dWeffK, *dQp, *dKp, *dV, *dO;
    cudaGetSymbolAddress((void**)&dWeffQ, g_WeffQ);
    cudaGetSymbolAddress((void**)&dWeffK, g_WeffK);
    cudaGetSymbolAddress((void**)&dQp,    g_Qp);
    cudaGetSymbolAddress((void**)&dKp,    g_Kp);
    cudaGetSymbolAddress((void**)&dV,     g_V);
    cudaGetSymbolAddress((void**)&dO,     g_O);

    // 1) fold S into projection weights
    weff_kernel<<<dim3(DD/256, HH, 2), 256>>>(Wq, Wk, Sq, Sk);

    // 2) projections: Qp = x @ WeffQ^T, Kp = x @ WeffK^T, V = x @ Wv^T
    dim3 ggrid(DD/128, MM/128);
    gemm_nt_kernel<<<ggrid, 256>>>(x, dWeffQ, dQp);
    gemm_nt_kernel<<<ggrid, 256>>>(x, dWeffK, dKp);
    gemm_nt_kernel<<<ggrid, 256>>>(x, Wv, dV);

    // 3) attention (mask is all-true)
    attn_kernel<<<dim3(TT/128, BB*HH), 128>>>();

    // 4) output projection: out = O @ Wo^T
    gemm_nt_kernel<<<ggrid, 256>>>(dO, Wo, outp);
}

// round 6
// speedup vs baseline: 3.9446x; 3.9446x over previous
#include <cuda_runtime.h>
#include <cuda_bf16.h>
#include <cuda_fp16.h>
#include <math.h>
#include <stdint.h>

// Shapes (fixed)
#define BB 2
#define TT 2048
#define DD 1024
#define HH 16
#define DH 64
#define MM (BB*TT)   // 4096
#define BH (BB*HH)   // 32

// ---------------------------------------------------------------------------
// Scratch (no cudaMalloc allowed)
// ---------------------------------------------------------------------------
__device__ float g_WeffQ[DD*DD];
__device__ float g_WeffK[DD*DD];
__device__ float g_Qp[MM*DD];
__device__ float g_Kp[MM*DD];
__device__ float g_V [MM*DD];
__device__ float g_O [MM*DD];
// bf16 hi/lo split GEMM operands: [rows][2048] = [hi(1024) | lo(1024)]
__device__ __nv_bfloat16 g_A2 [MM*2*DD];
__device__ __nv_bfloat16 g_O2 [MM*2*DD];
__device__ __nv_bfloat16 g_WQ2[DD*2*DD];
__device__ __nv_bfloat16 g_WK2[DD*2*DD];
__device__ __nv_bfloat16 g_WV2[DD*2*DD];
__device__ __nv_bfloat16 g_WO2[DD*2*DD];
// attention operands
__device__ __nv_bfloat16 g_Qs[BH*TT*128];    // [bh][t][hi64|lo64], Q pre-scaled
__device__ __nv_bfloat16 g_Ks[BH*TT*128];    // [bh][t][hi64|lo64]
__device__ __half        g_Vt[BH*2*DH*TT];   // [bh][hi/lo][d][s]  (transposed)

// ---------------------------------------------------------------------------
// PTX helpers (sm_80-level only: NO tcgen05 / TMA — ptxas targets plain sm_103)
// ---------------------------------------------------------------------------
__device__ __forceinline__ uint32_t smem_u32(const void* p) {
    uint32_t a;
    asm("{ .reg .u64 t; cvta.to.shared.u64 t, %1; cvt.u32.u64 %0, t; }" : "=r"(a) : "l"(p));
    return a;
}
__device__ __forceinline__ void cp_async16(uint32_t dst, const void* src) {
    asm volatile("cp.async.cg.shared.global [%0], [%1], 16;\n" :: "r"(dst), "l"(src));
}
#define CP_COMMIT() asm volatile("cp.async.commit_group;\n" ::: "memory")
#define CP_WAIT1()  asm volatile("cp.async.wait_group 1;\n" ::: "memory")

__device__ __forceinline__ void ldsm4(uint32_t &r0, uint32_t &r1, uint32_t &r2, uint32_t &r3,
                                      uint32_t addr) {
    asm volatile("ldmatrix.sync.aligned.m8n8.x4.shared.b16 {%0,%1,%2,%3}, [%4];"
                 : "=r"(r0), "=r"(r1), "=r"(r2), "=r"(r3) : "r"(addr));
}
__device__ __forceinline__ void mma_bf16(float* c, const uint32_t* a, const uint32_t* b) {
    asm volatile("mma.sync.aligned.m16n8k16.row.col.f32.bf16.bf16.f32 "
                 "{%0,%1,%2,%3}, {%4,%5,%6,%7}, {%8,%9}, {%0,%1,%2,%3};"
                 : "+f"(c[0]), "+f"(c[1]), "+f"(c[2]), "+f"(c[3])
                 : "r"(a[0]), "r"(a[1]), "r"(a[2]), "r"(a[3]), "r"(b[0]), "r"(b[1]));
}
__device__ __forceinline__ void mma_f16(float* c, const uint32_t* a, const uint32_t* b) {
    asm volatile("mma.sync.aligned.m16n8k16.row.col.f32.f16.f16.f32 "
                 "{%0,%1,%2,%3}, {%4,%5,%6,%7}, {%8,%9}, {%0,%1,%2,%3};"
                 : "+f"(c[0]), "+f"(c[1]), "+f"(c[2]), "+f"(c[3])
                 : "r"(a[0]), "r"(a[1]), "r"(a[2]), "r"(a[3]), "r"(b[0]), "r"(b[1]));
}
__device__ __forceinline__ float ex2f(float x) {
    float r; asm("ex2.approx.ftz.f32 %0, %1;" : "=f"(r) : "f"(x)); return r;
}
__device__ __forceinline__ uint32_t ex2_h2(uint32_t x) {
    uint32_t r; asm("ex2.approx.f16x2 %0, %1;" : "=r"(r) : "r"(x)); return r;
}
__device__ __forceinline__ uint32_t f2h2u(float a, float b) {
    __half2 h = __floats2half2_rn(a, b);
    return *reinterpret_cast<uint32_t*>(&h);
}
__device__ __forceinline__ float2 h2u2f2(uint32_t u) {
    __half2 h = *reinterpret_cast<__half2*>(&u);
    return __half22float2(h);
}

// ---------------------------------------------------------------------------
// Weff fold: WeffT[h*64+e][d] = sum_c W[h*64+c][d] * S[h][c][e]
// ---------------------------------------------------------------------------
__global__ __launch_bounds__(256)
void weff_kernel(const float* __restrict__ Wq, const float* __restrict__ Wk,
                 const float* __restrict__ Sq, const float* __restrict__ Sk)
{
    const int h = blockIdx.y;
    const bool isK = (blockIdx.z != 0);
    const float* __restrict__ W = isK ? Wk : Wq;
    const float* __restrict__ S = isK ? Sk : Sq;
    float* __restrict__ outp = isK ? g_WeffK : g_WeffQ;

    __shared__ float s_s[DH*DH];
    for (int i = threadIdx.x; i < DH*DH; i += 256) s_s[i] = S[h*DH*DH + i];
    __syncthreads();

    const int d = blockIdx.x * 256 + threadIdx.x;
    float acc[DH];
#pragma unroll
    for (int e = 0; e < DH; e++) acc[e] = 0.f;
    for (int c = 0; c < DH; c++) {
        const float w = W[(h*DH + c)*DD + d];
#pragma unroll
        for (int e = 0; e < DH; e++) acc[e] += w * s_s[c*DH + e];
    }
#pragma unroll
    for (int e = 0; e < DH; e++) outp[(h*DH + e)*DD + d] = acc[e];
}

// ---------------------------------------------------------------------------
// fp32 -> bf16 hi/lo split for GEMM operands: [rows][1024] -> [rows][2048]
// ---------------------------------------------------------------------------
__global__ __launch_bounds__(256)
void cvt_split_kernel(const float* __restrict__ src, __nv_bfloat16* __restrict__ dst, int n)
{
    int i = blockIdx.x * 256 + threadIdx.x;
    if (i >= n) return;
    int r = i >> 10, c = i & 1023;
    float v = src[i];
    __nv_bfloat16 hi = __float2bfloat16(v);
    float lof = v - __bfloat162float(hi);
    dst[(size_t)r*2048 + c] = hi;
    dst[(size_t)r*2048 + 1024 + c] = __float2bfloat16(lof);
}

// ---------------------------------------------------------------------------
// attention-layout cvt: fp32 [(b t)][(h e)] -> bf16 [bh][t][hi64|lo64], scaled
// ---------------------------------------------------------------------------
__global__ __launch_bounds__(256)
void cvt_qk_kernel(const float* __restrict__ src, __nv_bfloat16* __restrict__ dst, float scale)
{
    int i = blockIdx.x * 256 + threadIdx.x;
    if (i >= MM*DD) return;
    int r = i >> 10, c = i & 1023;
    int h = c >> 6, e = c & 63;
    int b = r >> 11, t = r & 2047;
    float v = src[i] * scale;
    __nv_bfloat16 hi = __float2bfloat16(v);
    float lof = v - __bfloat162float(hi);
    size_t base = ((size_t)(b*HH + h)*TT + t) << 7;
    dst[base + e] = hi;
    dst[base + 64 + e] = __float2bfloat16(lof);
}

// ---------------------------------------------------------------------------
// V transpose + f16 hi/lo: fp32 [(b s)][(h d)] -> f16 [bh][hi/lo][d][s]
// grid (T/64, BH), 256 threads; smem tile 64x64
// ---------------------------------------------------------------------------
__global__ __launch_bounds__(256)
void cvt_vt_kernel(const float* __restrict__ V)
{
    __shared__ float tile[64][65];
    const int bh = blockIdx.y;
    const int b = bh >> 4, h = bh & 15;
    const int s0 = blockIdx.x * 64;

    for (int i = threadIdx.x; i < 64*64; i += 256) {
        int si = i >> 6, d = i & 63;
        tile[si][d] = V[((size_t)(b*TT + s0 + si))*DD + h*DH + d];
    }
    __syncthreads();
    __half* dh = g_Vt + ((size_t)(bh*2    ) * DH) * TT;
    __half* dl = g_Vt + ((size_t)(bh*2 + 1) * DH) * TT;
    for (int i = threadIdx.x; i < 64*64; i += 256) {
        int d = i >> 6, s = i & 63;
        float v = tile[s][d];
        __half hi = __float2half_rn(v);
        __half lo = __float2half_rn(v - __half2float(hi));
        dh[(size_t)d*TT + s0 + s] = hi;
        dl[(size_t)d*TT + s0 + s] = lo;
    }
}

// ---------------------------------------------------------------------------
// HMMA NT GEMM: C[4096x1024] = A @ Bt^T, bf16 3-term hi/lo (eff K=3072).
// CTA 128x128, 8 warps (warp tile 32x64), BK=64, 3-stage cp.async.
// grid (8, 32), 256 threads. smem row stride 144B (conflict-free ldmatrix).
// ---------------------------------------------------------------------------
#define G_TILEB  (128*144)          // 18432 per operand tile
#define G_STAGEB (2*G_TILEB)
#define G_SMEM   (3*G_STAGEB)       // 110592

__global__ __launch_bounds__(256, 1)
void gemm_mma_kernel(const __nv_bfloat16* __restrict__ A2,
                     const __nv_bfloat16* __restrict__ B2,
                     float* __restrict__ C)
{
    extern __shared__ char smraw[];
    const uint32_t sbase = smem_u32(smraw);
    const int tid = threadIdx.x;
    const int wid = tid >> 5, lane = tid & 31;
    const int warp_m = wid >> 1, warp_n = wid & 1;
    const int m0 = blockIdx.y * 128, n0 = blockIdx.x * 128;

    float acc[2][8][4];
#pragma unroll
    for (int a = 0; a < 2; a++)
#pragma unroll
        for (int b = 0; b < 8; b++)
#pragma unroll
            for (int c = 0; c < 4; c++) acc[a][b][c] = 0.f;

    auto LOAD = [&](int it) {
        const int term = it >> 4, kk = (it & 15) << 6;
        const char* gA = (const char*)(A2 + (size_t)m0*2048 + ((term == 2) ? 1024 : 0) + kk);
        const char* gB = (const char*)(B2 + (size_t)n0*2048 + ((term == 1) ? 1024 : 0) + kk);
        const uint32_t sA = sbase + (it % 3) * G_STAGEB;
        const uint32_t sB = sA + G_TILEB;
#pragma unroll
        for (int i = 0; i < 4; i++) {
            int u = tid + i*256;
            int row = u >> 3, kb = (u & 7) << 4;
            cp_async16(sA + row*144 + kb, gA + (size_t)row*4096 + kb);
        }
#pragma unroll
        for (int i = 0; i < 4; i++) {
            int u = tid + i*256;
            int row = u >> 3, kb = (u & 7) << 4;
            cp_async16(sB + row*144 + kb, gB + (size_t)row*4096 + kb);
        }
    };

    LOAD(0); CP_COMMIT();
    LOAD(1); CP_COMMIT();

    const int NIT = 48;
    for (int it = 0; it < NIT; it++) {
        CP_WAIT1();
        __syncthreads();
        const uint32_t sA = sbase + (it % 3) * G_STAGEB;
        const uint32_t sB = sA + G_TILEB;
#pragma unroll
        for (int j = 0; j < 4; j++) {
            uint32_t a[2][4];
#pragma unroll
            for (int mf = 0; mf < 2; mf++) {
                uint32_t addr = sA + (warp_m*32 + mf*16 + (lane & 15))*144
                              + j*32 + ((lane >> 4) << 4);
                ldsm4(a[mf][0], a[mf][1], a[mf][2], a[mf][3], addr);
            }
            uint32_t b[8][2];
#pragma unroll
            for (int nf2 = 0; nf2 < 4; nf2++) {
                uint32_t r0, r1, r2, r3;
                uint32_t addr = sB + (warp_n*64 + nf2*16 + (lane & 15))*144
                              + j*32 + ((lane >> 4) << 4);
                ldsm4(r0, r1, r2, r3, addr);
                b[nf2*2  ][0] = r0; b[nf2*2  ][1] = r2;
                b[nf2*2+1][0] = r1; b[nf2*2+1][1] = r3;
            }
#pragma unroll
            for (int mf = 0; mf < 2; mf++)
#pragma unroll
                for (int nf = 0; nf < 8; nf++)
                    mma_bf16(acc[mf][nf], a[mf], b[nf]);
        }
        __syncthreads();
        if (it + 2 < NIT) LOAD(it + 2);
        CP_COMMIT();
    }

    const int g = lane >> 2, t = lane & 3;
#pragma unroll
    for (int mf = 0; mf < 2; mf++) {
        int row0 = m0 + warp_m*32 + mf*16 + g;
#pragma unroll
        for (int nf = 0; nf < 8; nf++) {
            int col = n0 + warp_n*64 + nf*8 + t*2;
            *(float2*)&C[(size_t)row0*DD + col]     = make_float2(acc[mf][nf][0], acc[mf][nf][1]);
            *(float2*)&C[(size_t)(row0+8)*DD + col] = make_float2(acc[mf][nf][2], acc[mf][nf][3]);
        }
    }
}

// ---------------------------------------------------------------------------
// Flash attention on HMMA.
// CTA: one (b,h) x 128 queries; 8 warps, warp = 16 queries.
// QK: bf16 3-term (Q pre-scaled by 0.125*log2e -> exp2 domain).
// softmax: ex2.approx.f16x2; P native f16; PV: f16, V hi/lo 2-term.
// K chunks of 64 keys, double-buffered cp.async.
// grid (16, 32), 256 threads.
// ---------------------------------------------------------------------------
#define AT_QSTRIDE 272
#define AT_QBYTES  (128*272)        // 34816
#define AT_ARR     (64*144)         // 9216 per sub-array
#define AT_STAGEB  (4*AT_ARR)       // Khi,Klo,Vhi,Vlo
#define AT_SMEM    (AT_QBYTES + 2*AT_STAGEB)  // 108544

__global__ __launch_bounds__(256, 1)
void attn_mma_kernel(float* __restrict__ O)
{
    extern __shared__ char smraw[];
    const uint32_t sbase = smem_u32(smraw);
    const int tid = threadIdx.x, wid = tid >> 5, lane = tid & 31;
    const int bh = blockIdx.y;
    const int q0 = blockIdx.x * 128;

    const char* Qbase = (const char*)(g_Qs + ((size_t)bh*TT + q0) * 128);
    const char* Kbase = (const char*)(g_Ks + (size_t)bh*TT*128);
    const char* Vh    = (const char*)(g_Vt + ((size_t)(bh*2    )*DH)*TT);
    const char* Vl    = (const char*)(g_Vt + ((size_t)(bh*2 + 1)*DH)*TT);

    // Q tile -> smem (group 0)
#pragma unroll
    for (int i = 0; i < 8; i++) {
        int u = tid + i*256;               // 0..2047 units of 16B
        int row = u >> 4, cb = (u & 15) << 4;
        cp_async16(sbase + row*AT_QSTRIDE + cb, Qbase + (size_t)row*256 + cb);
    }
    CP_COMMIT();

    auto LOADC = [&](int c) {
        const uint32_t s = sbase + AT_QBYTES + (c & 1) * AT_STAGEB;
        const char* ksrc = Kbase + (size_t)c*64*256;
        const char* vhs  = Vh + (size_t)c*128;    // 64 f16 = 128B per chunk col-slice
        const char* vls  = Vl + (size_t)c*128;
#pragma unroll
        for (int i = 0; i < 2; i++) {
            int u = tid + i*256;                   // 0..511
            int r = u >> 3, kb = (u & 7) << 4;
            cp_async16(s            + r*144 + kb, ksrc + (size_t)r*256 + kb);        // Khi
            cp_async16(s +   AT_ARR + r*144 + kb, ksrc + (size_t)r*256 + 128 + kb);  // Klo
            cp_async16(s + 2*AT_ARR + r*144 + kb, vhs + (size_t)r*4096 + kb);        // Vhi [d][s]
            cp_async16(s + 3*AT_ARR + r*144 + kb, vls + (size_t)r*4096 + kb);        // Vlo
        }
    };

    LOADC(0); CP_COMMIT();
    CP_WAIT1();            // Q (group 0) resident
    __syncthreads();

    // Q fragments (held in registers for the whole kernel)
    uint32_t qh[4][4], ql[4][4];
#pragma unroll
    for (int j = 0; j < 4; j++) {
        uint32_t base = sbase + (wid*16 + (lane & 15))*AT_QSTRIDE + j*32 + ((lane >> 4) << 4);
        ldsm4(qh[j][0], qh[j][1], qh[j][2], qh[j][3], base);
        ldsm4(ql[j][0], ql[j][1], ql[j][2], ql[j][3], base + 128);
    }

    float of[8][4];
#pragma unroll
    for (int f = 0; f < 8; f++)
#pragma unroll
        for (int c = 0; c < 4; c++) of[f][c] = 0.f;
    float m0 = -1e30f, m1 = -1e30f, l0 = 0.f, l1 = 0.f;

    for (int c = 0; c < 32; c++) {
        if (c + 1 < 32) LOADC(c + 1);
        CP_COMMIT();
        CP_WAIT1();
        __syncthreads();

        const uint32_t sK  = sbase + AT_QBYTES + (c & 1) * AT_STAGEB;
        const uint32_t sKl = sK + AT_ARR, sVh = sK + 2*AT_ARR, sVl = sK + 3*AT_ARR;

        // ---- scores (exp2 domain; scale folded into Q) ----
        float sfr[8][4];
#pragma unroll
        for (int f = 0; f < 8; f++)
#pragma unroll
            for (int r = 0; r < 4; r++) sfr[f][r] = 0.f;

#pragma unroll
        for (int j = 0; j < 4; j++) {
            const uint32_t cb = j*32 + ((lane >> 4) << 4);
            uint32_t b[8][2];
#pragma unroll
            for (int nf2 = 0; nf2 < 4; nf2++) {       // K hi
                uint32_t r0, r1, r2, r3;
                ldsm4(r0, r1, r2, r3, sK + (nf2*16 + (lane & 15))*144 + cb);
                b[nf2*2][0] = r0; b[nf2*2][1] = r2;
                b[nf2*2+1][0] = r1; b[nf2*2+1][1] = r3;
            }
#pragma unroll
            for (int nf = 0; nf < 8; nf++) {
                mma_bf16(sfr[nf], qh[j], b[nf]);      // Qhi * Khi
                mma_bf16(sfr[nf], ql[j], b[nf]);      // Qlo * Khi
            }
#pragma unroll
            for (int nf2 = 0; nf2 < 4; nf2++) {       // K lo
                uint32_t r0, r1, r2, r3;
                ldsm4(r0, r1, r2, r3, sKl + (nf2*16 + (lane & 15))*144 + cb);
                b[nf2*2][0] = r0; b[nf2*2][1] = r2;
                b[nf2*2+1][0] = r1; b[nf2*2+1][1] = r3;
            }
#pragma unroll
            for (int nf = 0; nf < 8; nf++)
                mma_bf16(sfr[nf], qh[j], b[nf]);      // Qhi * Klo
        }

        // ---- online softmax ----
        float mx0 = sfr[0][0], mx1 = sfr[0][2];
#pragma unroll
        for (int f = 0; f < 8; f++) {
            mx0 = fmaxf(mx0, fmaxf(sfr[f][0], sfr[f][1]));
            mx1 = fmaxf(mx1, fmaxf(sfr[f][2], sfr[f][3]));
        }
        mx0 = fmaxf(mx0, __shfl_xor_sync(0xffffffffu, mx0, 1));
        mx0 = fmaxf(mx0, __shfl_xor_sync(0xffffffffu, mx0, 2));
        mx1 = fmaxf(mx1, __shfl_xor_sync(0xffffffffu, mx1, 1));
        mx1 = fmaxf(mx1, __shfl_xor_sync(0xffffffffu, mx1, 2));
        const float m0n = fmaxf(m0, mx0), m1n = fmaxf(m1, mx1);
        const float corr0 = ex2f(m0 - m0n), corr1 = ex2f(m1 - m1n);

        uint32_t pa[4][4];
        float l0a = 0.f, l1a = 0.f;
#pragma unroll
        for (int f = 0; f < 8; f++) {
            uint32_t p01 = ex2_h2(f2h2u(sfr[f][0] - m0n, sfr[f][1] - m0n));
            uint32_t p23 = ex2_h2(f2h2u(sfr[f][2] - m1n, sfr[f][3] - m1n));
            const int j = f >> 1;
            if (f & 1) { pa[j][2] = p01; pa[j][3] = p23; }
            else       { pa[j][0] = p01; pa[j][1] = p23; }
            float2 a = h2u2f2(p01); l0a += a.x + a.y;
            float2 bsum = h2u2f2(p23); l1a += bsum.x + bsum.y;
        }
        l0a += __shfl_xor_sync(0xffffffffu, l0a, 1);
        l0a += __shfl_xor_sync(0xffffffffu, l0a, 2);
        l1a += __shfl_xor_sync(0xffffffffu, l1a, 1);
        l1a += __shfl_xor_sync(0xffffffffu, l1a, 2);
        l0 = l0 * corr0 + l0a;
        l1 = l1 * corr1 + l1a;
        m0 = m0n; m1 = m1n;

#pragma unroll
        for (int f = 0; f < 8; f++) {
            of[f][0] *= corr0; of[f][1] *= corr0;
            of[f][2] *= corr1; of[f][3] *= corr1;
        }

        // ---- PV (f16): O += P*Vhi + P*Vlo ----
#pragma unroll
        for (int j = 0; j < 4; j++) {
            const uint32_t cb = j*32 + ((lane >> 4) << 4);
            uint32_t b[8][2];
#pragma unroll
            for (int nf2 = 0; nf2 < 4; nf2++) {       // V hi: rows = d
                uint32_t r0, r1, r2, r3;
                ldsm4(r0, r1, r2, r3, sVh + (nf2*16 + (lane & 15))*144 + cb);
                b[nf2*2][0] = r0; b[nf2*2][1] = r2;
                b[nf2*2+1][0] = r1; b[nf2*2+1][1] = r3;
            }
#pragma unroll
            for (int nf = 0; nf < 8; nf++)
                mma_f16(of[nf], pa[j], b[nf]);
#pragma unroll
            for (int nf2 = 0; nf2 < 4; nf2++) {       // V lo
                uint32_t r0, r1, r2, r3;
                ldsm4(r0, r1, r2, r3, sVl + (nf2*16 + (lane & 15))*144 + cb);
                b[nf2*2][0] = r0; b[nf2*2][1] = r2;
                b[nf2*2+1][0] = r1; b[nf2*2+1][1] = r3;
            }
#pragma unroll
            for (int nf = 0; nf < 8; nf++)
                mma_f16(of[nf], pa[j], b[nf]);
        }
        __syncthreads();
    }

    // epilogue: O[q][d] / l  ->  g_O[(b t)][(h d)]
    const float inv0 = 1.f / l0, inv1 = 1.f / l1;
    const int b = bh >> 4, h = bh & 15;
    const int g = lane >> 2, t = lane & 3;
    const int qrow = q0 + wid*16 + g;
    float* Op = O + ((size_t)(b*TT) + qrow)*DD + h*DH + t*2;
#pragma unroll
    for (int f = 0; f < 8; f++) {
        *(float2*)&Op[f*8]           = make_float2(of[f][0]*inv0, of[f][1]*inv0);
        *(float2*)&Op[8*DD + f*8]    = make_float2(of[f][2]*inv1, of[f][3]*inv1);
    }
}

// ---------------------------------------------------------------------------
// Launch. Inputs: 0=x, 1=mask, 2=Wq, 3=Wk, 4=Wv, 5=Wo, 6=S_q, 7=S_k
// ---------------------------------------------------------------------------
extern "C" void kernel_launch(void* const* d_in, const int* in_sizes, int n_in,
                              void* d_out, int out_size)
{
    const float* x  = (const float*)d_in[0];
    const float* Wq = (const float*)d_in[2];
    const float* Wk = (const float*)d_in[3];
    const float* Wv = (const float*)d_in[4];
    const float* Wo = (const float*)d_in[5];
    const float* Sq = (const float*)d_in[6];
    const float* Sk = (const float*)d_in[7];
    float* outp = (float*)d_out;

    float *dWeffQ, *dWeffK, *dQp, *dKp, *dV, *dO;
    __nv_bfloat16 *dA2, *dO2, *dWQ2, *dWK2, *dWV2, *dWO2, *dQs, *dKs;
    cudaGetSymbolAddress((void**)&dWeffQ, g_WeffQ);
    cudaGetSymbolAddress((void**)&dWeffK, g_WeffK);
    cudaGetSymbolAddress((void**)&dQp,    g_Qp);
    cudaGetSymbolAddress((void**)&dKp,    g_Kp);
    cudaGetSymbolAddress((void**)&dV,     g_V);
    cudaGetSymbolAddress((void**)&dO,     g_O);
    cudaGetSymbolAddress((void**)&dA2,    g_A2);
    cudaGetSymbolAddress((void**)&dO2,    g_O2);
    cudaGetSymbolAddress((void**)&dWQ2,   g_WQ2);
    cudaGetSymbolAddress((void**)&dWK2,   g_WK2);
    cudaGetSymbolAddress((void**)&dWV2,   g_WV2);
    cudaGetSymbolAddress((void**)&dWO2,   g_WO2);
    cudaGetSymbolAddress((void**)&dQs,    g_Qs);
    cudaGetSymbolAddress((void**)&dKs,    g_Ks);

    cudaFuncSetAttribute(gemm_mma_kernel, cudaFuncAttributeMaxDynamicSharedMemorySize, G_SMEM);
    cudaFuncSetAttribute(attn_mma_kernel, cudaFuncAttributeMaxDynamicSharedMemorySize, AT_SMEM);

    // 1) fold S into projection weights (fp32)
    weff_kernel<<<dim3(DD/256, HH, 2), 256>>>(Wq, Wk, Sq, Sk);

    // 2) bf16 hi/lo splits of x and weights
    cvt_split_kernel<<<(MM*DD)/256, 256>>>(x,      dA2,  MM*DD);
    cvt_split_kernel<<<(DD*DD)/256, 256>>>(dWeffQ, dWQ2, DD*DD);
    cvt_split_kernel<<<(DD*DD)/256, 256>>>(dWeffK, dWK2, DD*DD);
    cvt_split_kernel<<<(DD*DD)/256, 256>>>(Wv,     dWV2, DD*DD);
    cvt_split_kernel<<<(DD*DD)/256, 256>>>(Wo,     dWO2, DD*DD);

    // 3) projections (HMMA)
    dim3 ggrid(DD/128, MM/128);   // (8, 32)
    gemm_mma_kernel<<<ggrid, 256, G_SMEM>>>(dA2, dWQ2, dQp);
    gemm_mma_kernel<<<ggrid, 256, G_SMEM>>>(dA2, dWK2, dKp);
    gemm_mma_kernel<<<ggrid, 256, G_SMEM>>>(dA2, dWV2, dV);

    // 4) attention-layout conversions (Q pre-scaled into exp2 domain)
    const float qscale = 0.125f * 1.4426950408889634f;
    cvt_qk_kernel<<<(MM*DD)/256, 256>>>(dQp, dQs, qscale);
    cvt_qk_kernel<<<(MM*DD)/256, 256>>>(dKp, dKs, 1.0f);
    cvt_vt_kernel<<<dim3(TT/64, BH), 256>>>(dV);

    // 5) flash attention (HMMA; mask all-true)
    attn_mma_kernel<<<dim3(TT/128, BH), 256, AT_SMEM>>>(dO);

    // 6) output projection (HMMA)
    cvt_split_kernel<<<(MM*DD)/256, 256>>>(dO, dO2, MM*DD);
    gemm_mma_kernel<<<ggrid, 256, G_SMEM>>>(dO2, dWO2, outp);
}

// round 7
// speedup vs baseline: 4.1250x; 1.0457x over previous
#include <cuda_runtime.h>
#include <cuda_bf16.h>
#include <cuda_fp16.h>
#include <math.h>
#include <stdint.h>

// Shapes (fixed)
#define BB 2
#define TT 2048
#define DD 1024
#define HH 16
#define DH 64
#define MM (BB*TT)   // 4096
#define BH (BB*HH)   // 32

// ---------------------------------------------------------------------------
// Scratch (no cudaMalloc allowed)
// ---------------------------------------------------------------------------
__device__ float g_V [MM*DD];                 // V projection (fp32, for transpose)
// bf16 hi/lo split GEMM operands: [rows][2048] = [hi(1024) | lo(1024)]
__device__ __nv_bfloat16 g_A2 [MM*2*DD];      // x split
__device__ __nv_bfloat16 g_O2 [MM*2*DD];      // attention output split (written by attn)
__device__ __nv_bfloat16 g_WQ2[DD*2*DD];      // folded Wq split (written by weff)
__device__ __nv_bfloat16 g_WK2[DD*2*DD];      // folded Wk split (written by weff)
__device__ __nv_bfloat16 g_WV2[DD*2*DD];
__device__ __nv_bfloat16 g_WO2[DD*2*DD];
// attention operands
__device__ __nv_bfloat16 g_Qs[BH*TT*128];     // [bh][t][hi64|lo64], Q pre-scaled
__device__ __nv_bfloat16 g_Ks[BH*TT*128];     // [bh][t][hi64|lo64]
__device__ __half        g_Vt[BH*2*DH*TT];    // [bh][hi/lo][d][s] (transposed)

// ---------------------------------------------------------------------------
// PTX helpers (sm_80-level only — ptxas targets plain sm_103, no tcgen05/TMA)
// ---------------------------------------------------------------------------
__device__ __forceinline__ uint32_t smem_u32(const void* p) {
    uint32_t a;
    asm("{ .reg .u64 t; cvta.to.shared.u64 t, %1; cvt.u32.u64 %0, t; }" : "=r"(a) : "l"(p));
    return a;
}
__device__ __forceinline__ void cp_async16(uint32_t dst, const void* src) {
    asm volatile("cp.async.cg.shared.global [%0], [%1], 16;\n" :: "r"(dst), "l"(src));
}
#define CP_COMMIT() asm volatile("cp.async.commit_group;\n" ::: "memory")
#define CP_WAIT1()  asm volatile("cp.async.wait_group 1;\n" ::: "memory")

__device__ __forceinline__ void ldsm4(uint32_t &r0, uint32_t &r1, uint32_t &r2, uint32_t &r3,
                                      uint32_t addr) {
    asm volatile("ldmatrix.sync.aligned.m8n8.x4.shared.b16 {%0,%1,%2,%3}, [%4];"
                 : "=r"(r0), "=r"(r1), "=r"(r2), "=r"(r3) : "r"(addr));
}
__device__ __forceinline__ void mma_bf16(float* c, const uint32_t* a, const uint32_t* b) {
    asm volatile("mma.sync.aligned.m16n8k16.row.col.f32.bf16.bf16.f32 "
                 "{%0,%1,%2,%3}, {%4,%5,%6,%7}, {%8,%9}, {%0,%1,%2,%3};"
                 : "+f"(c[0]), "+f"(c[1]), "+f"(c[2]), "+f"(c[3])
                 : "r"(a[0]), "r"(a[1]), "r"(a[2]), "r"(a[3]), "r"(b[0]), "r"(b[1]));
}
__device__ __forceinline__ void mma_f16(float* c, const uint32_t* a, const uint32_t* b) {
    asm volatile("mma.sync.aligned.m16n8k16.row.col.f32.f16.f16.f32 "
                 "{%0,%1,%2,%3}, {%4,%5,%6,%7}, {%8,%9}, {%0,%1,%2,%3};"
                 : "+f"(c[0]), "+f"(c[1]), "+f"(c[2]), "+f"(c[3])
                 : "r"(a[0]), "r"(a[1]), "r"(a[2]), "r"(a[3]), "r"(b[0]), "r"(b[1]));
}
__device__ __forceinline__ float ex2f(float x) {
    float r; asm("ex2.approx.ftz.f32 %0, %1;" : "=f"(r) : "f"(x)); return r;
}
__device__ __forceinline__ uint32_t ex2_h2(uint32_t x) {
    uint32_t r; asm("ex2.approx.f16x2 %0, %1;" : "=r"(r) : "r"(x)); return r;
}
__device__ __forceinline__ uint32_t f2h2u(float a, float b) {
    __half2 h = __floats2half2_rn(a, b);
    return *reinterpret_cast<uint32_t*>(&h);
}
__device__ __forceinline__ float2 h2u2f2(uint32_t u) {
    __half2 h = *reinterpret_cast<__half2*>(&u);
    return __half22float2(h);
}
__device__ __forceinline__ uint32_t pack_bf16(float a, float b) {
    __nv_bfloat162 h = __floats2bfloat162_rn(a, b);
    return *reinterpret_cast<uint32_t*>(&h);
}
// split v into bf16 hi/lo pair packs for (v0,v1)
__device__ __forceinline__ void split2(float v0, float v1, uint32_t &hi, uint32_t &lo) {
    __nv_bfloat16 h0 = __float2bfloat16(v0);
    __nv_bfloat16 h1 = __float2bfloat16(v1);
    float l0 = v0 - __bfloat162float(h0);
    float l1 = v1 - __bfloat162float(h1);
    uint32_t u0 = (uint32_t)*reinterpret_cast<uint16_t*>(&h0);
    uint32_t u1 = (uint32_t)*reinterpret_cast<uint16_t*>(&h1);
    hi = u0 | (u1 << 16);
    lo = pack_bf16(l0, l1);
}

// ---------------------------------------------------------------------------
// Weff fold + split: WeffT[h*64+e][d] = sum_c W[h*64+c][d] * S[h][c][e]
// writes bf16 hi/lo split layout [j][2048] directly.
// ---------------------------------------------------------------------------
__global__ __launch_bounds__(256)
void weff_kernel(const float* __restrict__ Wq, const float* __restrict__ Wk,
                 const float* __restrict__ Sq, const float* __restrict__ Sk)
{
    const int h = blockIdx.y;
    const bool isK = (blockIdx.z != 0);
    const float* __restrict__ W = isK ? Wk : Wq;
    const float* __restrict__ S = isK ? Sk : Sq;
    __nv_bfloat16* __restrict__ outp = isK ? g_WK2 : g_WQ2;

    __shared__ float s_s[DH*DH];
    for (int i = threadIdx.x; i < DH*DH; i += 256) s_s[i] = S[h*DH*DH + i];
    __syncthreads();

    const int d = blockIdx.x * 256 + threadIdx.x;
    float acc[DH];
#pragma unroll
    for (int e = 0; e < DH; e++) acc[e] = 0.f;
    for (int c = 0; c < DH; c++) {
        const float w = W[(h*DH + c)*DD + d];
#pragma unroll
        for (int e = 0; e < DH; e++) acc[e] += w * s_s[c*DH + e];
    }
#pragma unroll
    for (int e = 0; e < DH; e++) {
        float v = acc[e];
        __nv_bfloat16 hi = __float2bfloat16(v);
        float lo = v - __bfloat162float(hi);
        outp[(size_t)(h*DH + e)*2048 + d] = hi;
        outp[(size_t)(h*DH + e)*2048 + 1024 + d] = __float2bfloat16(lo);
    }
}

// ---------------------------------------------------------------------------
// fp32 -> bf16 hi/lo split: [rows][1024] -> [rows][2048]
// ---------------------------------------------------------------------------
__global__ __launch_bounds__(256)
void cvt_split_kernel(const float* __restrict__ src, __nv_bfloat16* __restrict__ dst, int n)
{
    int i = blockIdx.x * 256 + threadIdx.x;
    if (i >= n) return;
    int r = i >> 10, c = i & 1023;
    float v = src[i];
    __nv_bfloat16 hi = __float2bfloat16(v);
    float lof = v - __bfloat162float(hi);
    dst[(size_t)r*2048 + c] = hi;
    dst[(size_t)r*2048 + 1024 + c] = __float2bfloat16(lof);
}

// ---------------------------------------------------------------------------
// V transpose + f16 hi/lo: fp32 [(b s)][(h d)] -> f16 [bh][hi/lo][d][s]
// ---------------------------------------------------------------------------
__global__ __launch_bounds__(256)
void cvt_vt_kernel(const float* __restrict__ V)
{
    __shared__ float tile[64][65];
    const int bh = blockIdx.y;
    const int b = bh >> 4, h = bh & 15;
    const int s0 = blockIdx.x * 64;

    for (int i = threadIdx.x; i < 64*64; i += 256) {
        int si = i >> 6, d = i & 63;
        tile[si][d] = V[((size_t)(b*TT + s0 + si))*DD + h*DH + d];
    }
    __syncthreads();
    __half* dh = g_Vt + ((size_t)(bh*2    ) * DH) * TT;
    __half* dl = g_Vt + ((size_t)(bh*2 + 1) * DH) * TT;
    for (int i = threadIdx.x; i < 64*64; i += 256) {
        int d = i >> 6, s = i & 63;
        float v = tile[s][d];
        __half hi = __float2half_rn(v);
        __half lo = __float2half_rn(v - __half2float(hi));
        dh[(size_t)d*TT + s0 + s] = hi;
        dl[(size_t)d*TT + s0 + s] = lo;
    }
}

// ---------------------------------------------------------------------------
// HMMA NT GEMM, merged hi/lo stages: per k-chunk (64) load Ahi,Alo,Bhi,Blo
// once, run 3 term passes (AhiBhi + AhiBlo + AloBhi).  16 iterations.
// CTA 128x128, 8 warps (warp 32x64), 2-stage cp.async pipeline.
// MODE 0: fp32 C.  MODE 1: write g_Qs (scaled, split, attn layout).
// MODE 2: write g_Ks (split, attn layout).
// ---------------------------------------------------------------------------
#define G2_TILE  (128*144)          // 18432 per sub-tile
#define G2_STAGE (4*G2_TILE)        // Ahi,Alo,Bhi,Blo = 73728
#define G2_SMEM  (2*G2_STAGE)       // 147456

template<int MODE>
__global__ __launch_bounds__(256, 1)
void gemm_mma2_kernel(const __nv_bfloat16* __restrict__ A2,
                      const __nv_bfloat16* __restrict__ B2,
                      float* __restrict__ C, float scale)
{
    extern __shared__ char smraw[];
    const uint32_t sbase = smem_u32(smraw);
    const int tid = threadIdx.x;
    const int wid = tid >> 5, lane = tid & 31;
    const int warp_m = wid >> 1, warp_n = wid & 1;
    const int m0 = blockIdx.y * 128, n0 = blockIdx.x * 128;

    float acc[2][8][4];
#pragma unroll
    for (int a = 0; a < 2; a++)
#pragma unroll
        for (int b = 0; b < 8; b++)
#pragma unroll
            for (int c = 0; c < 4; c++) acc[a][b][c] = 0.f;

    auto LOAD = [&](int it) {
        const uint32_t st = sbase + (it & 1) * G2_STAGE;
        const char* gAh = (const char*)(A2 + (size_t)m0*2048 + it*64);
        const char* gBh = (const char*)(B2 + (size_t)n0*2048 + it*64);
#pragma unroll
        for (int i = 0; i < 4; i++) {
            int u = tid + i*256;
            int row = u >> 3, kb = (u & 7) << 4;
            const size_t go = (size_t)row*4096 + kb;
            const uint32_t so = row*144 + kb;
            cp_async16(st             + so, gAh + go);          // A hi
            cp_async16(st +   G2_TILE + so, gAh + 2048 + go);   // A lo
            cp_async16(st + 2*G2_TILE + so, gBh + go);          // B hi
            cp_async16(st + 3*G2_TILE + so, gBh + 2048 + go);   // B lo
        }
    };

    LOAD(0); CP_COMMIT();
    LOAD(1); CP_COMMIT();

    const int NIT = 16;
    for (int it = 0; it < NIT; it++) {
        CP_WAIT1();
        __syncthreads();
        const uint32_t st = sbase + (it & 1) * G2_STAGE;
#pragma unroll
        for (int j = 0; j < 4; j++) {
            const uint32_t cb = j*32 + ((lane >> 4) << 4);
            uint32_t ah[2][4], al[2][4];
#pragma unroll
            for (int mf = 0; mf < 2; mf++) {
                const uint32_t ro = (warp_m*32 + mf*16 + (lane & 15))*144 + cb;
                ldsm4(ah[mf][0], ah[mf][1], ah[mf][2], ah[mf][3], st + ro);
                ldsm4(al[mf][0], al[mf][1], al[mf][2], al[mf][3], st + G2_TILE + ro);
            }
            uint32_t bh[8][2], bl[8][2];
#pragma unroll
            for (int nf2 = 0; nf2 < 4; nf2++) {
                const uint32_t ro = (warp_n*64 + nf2*16 + (lane & 15))*144 + cb;
                uint32_t r0, r1, r2, r3;
                ldsm4(r0, r1, r2, r3, st + 2*G2_TILE + ro);
                bh[nf2*2][0] = r0; bh[nf2*2][1] = r2;
                bh[nf2*2+1][0] = r1; bh[nf2*2+1][1] = r3;
                ldsm4(r0, r1, r2, r3, st + 3*G2_TILE + ro);
                bl[nf2*2][0] = r0; bl[nf2*2][1] = r2;
                bl[nf2*2+1][0] = r1; bl[nf2*2+1][1] = r3;
            }
#pragma unroll
            for (int mf = 0; mf < 2; mf++)
#pragma unroll
                for (int nf = 0; nf < 8; nf++) {
                    mma_bf16(acc[mf][nf], ah[mf], bh[nf]);   // hi*hi
                    mma_bf16(acc[mf][nf], ah[mf], bl[nf]);   // hi*lo
                    mma_bf16(acc[mf][nf], al[mf], bh[nf]);   // lo*hi
                }
        }
        __syncthreads();
        if (it + 2 < NIT) LOAD(it + 2);
        CP_COMMIT();
    }

    const int g = lane >> 2, t = lane & 3;
#pragma unroll
    for (int mf = 0; mf < 2; mf++) {
        const int row0 = m0 + warp_m*32 + mf*16 + g;
#pragma unroll
        for (int nf = 0; nf < 8; nf++) {
            const int col = n0 + warp_n*64 + nf*8 + t*2;
            if (MODE == 0) {
                *(float2*)&C[(size_t)row0*DD + col]     = make_float2(acc[mf][nf][0], acc[mf][nf][1]);
                *(float2*)&C[(size_t)(row0+8)*DD + col] = make_float2(acc[mf][nf][2], acc[mf][nf][3]);
            } else {
                __nv_bfloat16* dst = (MODE == 1) ? g_Qs : g_Ks;
                const int h = col >> 6, e = col & 63;
#pragma unroll
                for (int rr = 0; rr < 2; rr++) {
                    const int row = row0 + rr*8;
                    const int b = row >> 11, tq = row & 2047;
                    const size_t base = ((size_t)(b*HH + h)*TT + tq) << 7;
                    uint32_t hi, lo;
                    split2(acc[mf][nf][rr*2] * scale, acc[mf][nf][rr*2+1] * scale, hi, lo);
                    *(uint32_t*)&dst[base + e]      = hi;
                    *(uint32_t*)&dst[base + 64 + e] = lo;
                }
            }
        }
    }
}

// ---------------------------------------------------------------------------
// Flash attention on HMMA (as R6) — epilogue now writes g_O2 split directly.
// ---------------------------------------------------------------------------
#define AT_QSTRIDE 272
#define AT_QBYTES  (128*272)
#define AT_ARR     (64*144)
#define AT_STAGEB  (4*AT_ARR)
#define AT_SMEM    (AT_QBYTES + 2*AT_STAGEB)

__global__ __launch_bounds__(256, 1)
void attn_mma_kernel()
{
    extern __shared__ char smraw[];
    const uint32_t sbase = smem_u32(smraw);
    const int tid = threadIdx.x, wid = tid >> 5, lane = tid & 31;
    const int bh = blockIdx.y;
    const int q0 = blockIdx.x * 128;

    const char* Qbase = (const char*)(g_Qs + ((size_t)bh*TT + q0) * 128);
    const char* Kbase = (const char*)(g_Ks + (size_t)bh*TT*128);
    const char* Vh    = (const char*)(g_Vt + ((size_t)(bh*2    )*DH)*TT);
    const char* Vl    = (const char*)(g_Vt + ((size_t)(bh*2 + 1)*DH)*TT);

#pragma unroll
    for (int i = 0; i < 8; i++) {
        int u = tid + i*256;
        int row = u >> 4, cb = (u & 15) << 4;
        cp_async16(sbase + row*AT_QSTRIDE + cb, Qbase + (size_t)row*256 + cb);
    }
    CP_COMMIT();

    auto LOADC = [&](int c) {
        const uint32_t s = sbase + AT_QBYTES + (c & 1) * AT_STAGEB;
        const char* ksrc = Kbase + (size_t)c*64*256;
        const char* vhs  = Vh + (size_t)c*128;
        const char* vls  = Vl + (size_t)c*128;
#pragma unroll
        for (int i = 0; i < 2; i++) {
            int u = tid + i*256;
            int r = u >> 3, kb = (u & 7) << 4;
            cp_async16(s            + r*144 + kb, ksrc + (size_t)r*256 + kb);
            cp_async16(s +   AT_ARR + r*144 + kb, ksrc + (size_t)r*256 + 128 + kb);
            cp_async16(s + 2*AT_ARR + r*144 + kb, vhs + (size_t)r*4096 + kb);
            cp_async16(s + 3*AT_ARR + r*144 + kb, vls + (size_t)r*4096 + kb);
        }
    };

    LOADC(0); CP_COMMIT();
    CP_WAIT1();
    __syncthreads();

    uint32_t qh[4][4], ql[4][4];
#pragma unroll
    for (int j = 0; j < 4; j++) {
        uint32_t base = sbase + (wid*16 + (lane & 15))*AT_QSTRIDE + j*32 + ((lane >> 4) << 4);
        ldsm4(qh[j][0], qh[j][1], qh[j][2], qh[j][3], base);
        ldsm4(ql[j][0], ql[j][1], ql[j][2], ql[j][3], base + 128);
    }

    float of[8][4];
#pragma unroll
    for (int f = 0; f < 8; f++)
#pragma unroll
        for (int c = 0; c < 4; c++) of[f][c] = 0.f;
    float m0 = -1e30f, m1 = -1e30f, l0 = 0.f, l1 = 0.f;

    for (int c = 0; c < 32; c++) {
        if (c + 1 < 32) LOADC(c + 1);
        CP_COMMIT();
        CP_WAIT1();
        __syncthreads();

        const uint32_t sK  = sbase + AT_QBYTES + (c & 1) * AT_STAGEB;
        const uint32_t sKl = sK + AT_ARR, sVh = sK + 2*AT_ARR, sVl = sK + 3*AT_ARR;

        float sfr[8][4];
#pragma unroll
        for (int f = 0; f < 8; f++)
#pragma unroll
            for (int r = 0; r < 4; r++) sfr[f][r] = 0.f;

#pragma unroll
        for (int j = 0; j < 4; j++) {
            const uint32_t cb = j*32 + ((lane >> 4) << 4);
            uint32_t b[8][2];
#pragma unroll
            for (int nf2 = 0; nf2 < 4; nf2++) {
                uint32_t r0, r1, r2, r3;
                ldsm4(r0, r1, r2, r3, sK + (nf2*16 + (lane & 15))*144 + cb);
                b[nf2*2][0] = r0; b[nf2*2][1] = r2;
                b[nf2*2+1][0] = r1; b[nf2*2+1][1] = r3;
            }
#pragma unroll
            for (int nf = 0; nf < 8; nf++) {
                mma_bf16(sfr[nf], qh[j], b[nf]);
                mma_bf16(sfr[nf], ql[j], b[nf]);
            }
#pragma unroll
            for (int nf2 = 0; nf2 < 4; nf2++) {
                uint32_t r0, r1, r2, r3;
                ldsm4(r0, r1, r2, r3, sKl + (nf2*16 + (lane & 15))*144 + cb);
                b[nf2*2][0] = r0; b[nf2*2][1] = r2;
                b[nf2*2+1][0] = r1; b[nf2*2+1][1] = r3;
            }
#pragma unroll
            for (int nf = 0; nf < 8; nf++)
                mma_bf16(sfr[nf], qh[j], b[nf]);
        }

        float mx0 = sfr[0][0], mx1 = sfr[0][2];
#pragma unroll
        for (int f = 0; f < 8; f++) {
            mx0 = fmaxf(mx0, fmaxf(sfr[f][0], sfr[f][1]));
            mx1 = fmaxf(mx1, fmaxf(sfr[f][2], sfr[f][3]));
        }
        mx0 = fmaxf(mx0, __shfl_xor_sync(0xffffffffu, mx0, 1));
        mx0 = fmaxf(mx0, __shfl_xor_sync(0xffffffffu, mx0, 2));
        mx1 = fmaxf(mx1, __shfl_xor_sync(0xffffffffu, mx1, 1));
        mx1 = fmaxf(mx1, __shfl_xor_sync(0xffffffffu, mx1, 2));
        const float m0n = fmaxf(m0, mx0), m1n = fmaxf(m1, mx1);
        const float corr0 = ex2f(m0 - m0n), corr1 = ex2f(m1 - m1n);

        uint32_t pa[4][4];
        float l0a = 0.f, l1a = 0.f;
#pragma unroll
        for (int f = 0; f < 8; f++) {
            uint32_t p01 = ex2_h2(f2h2u(sfr[f][0] - m0n, sfr[f][1] - m0n));
            uint32_t p23 = ex2_h2(f2h2u(sfr[f][2] - m1n, sfr[f][3] - m1n));
            const int j = f >> 1;
            if (f & 1) { pa[j][2] = p01; pa[j][3] = p23; }
            else       { pa[j][0] = p01; pa[j][1] = p23; }
            float2 a = h2u2f2(p01); l0a += a.x + a.y;
            float2 bsum = h2u2f2(p23); l1a += bsum.x + bsum.y;
        }
        l0a += __shfl_xor_sync(0xffffffffu, l0a, 1);
        l0a += __shfl_xor_sync(0xffffffffu, l0a, 2);
        l1a += __shfl_xor_sync(0xffffffffu, l1a, 1);
        l1a += __shfl_xor_sync(0xffffffffu, l1a, 2);
        l0 = l0 * corr0 + l0a;
        l1 = l1 * corr1 + l1a;
        m0 = m0n; m1 = m1n;

#pragma unroll
        for (int f = 0; f < 8; f++) {
            of[f][0] *= corr0; of[f][1] *= corr0;
            of[f][2] *= corr1; of[f][3] *= corr1;
        }

#pragma unroll
        for (int j = 0; j < 4; j++) {
            const uint32_t cb = j*32 + ((lane >> 4) << 4);
            uint32_t b[8][2];
#pragma unroll
            for (int nf2 = 0; nf2 < 4; nf2++) {
                uint32_t r0, r1, r2, r3;
                ldsm4(r0, r1, r2, r3, sVh + (nf2*16 + (lane & 15))*144 + cb);
                b[nf2*2][0] = r0; b[nf2*2][1] = r2;
                b[nf2*2+1][0] = r1; b[nf2*2+1][1] = r3;
            }
#pragma unroll
            for (int nf = 0; nf < 8; nf++)
                mma_f16(of[nf], pa[j], b[nf]);
#pragma unroll
            for (int nf2 = 0; nf2 < 4; nf2++) {
                uint32_t r0, r1, r2, r3;
                ldsm4(r0, r1, r2, r3, sVl + (nf2*16 + (lane & 15))*144 + cb);
                b[nf2*2][0] = r0; b[nf2*2][1] = r2;
                b[nf2*2+1][0] = r1; b[nf2*2+1][1] = r3;
            }
#pragma unroll
            for (int nf = 0; nf < 8; nf++)
                mma_f16(of[nf], pa[j], b[nf]);
        }
        __syncthreads();
    }

    // epilogue: write split O directly to g_O2 [row][2048]
    const float inv0 = 1.f / l0, inv1 = 1.f / l1;
    const int b = bh >> 4, h = bh & 15;
    const int g = lane >> 2, t = lane & 3;
    const int qrow = q0 + wid*16 + g;
#pragma unroll
    for (int f = 0; f < 8; f++) {
        const int col = h*DH + f*8 + t*2;
#pragma unroll
        for (int rr = 0; rr < 2; rr++) {
            const size_t row = (size_t)(b*TT) + qrow + rr*8;
            const float inv = rr ? inv1 : inv0;
            uint32_t hi, lo;
            split2(of[f][rr*2] * inv, of[f][rr*2+1] * inv, hi, lo);
            *(uint32_t*)&g_O2[row*2048 + col]        = hi;
            *(uint32_t*)&g_O2[row*2048 + 1024 + col] = lo;
        }
    }
}

// ---------------------------------------------------------------------------
// Launch. Inputs: 0=x, 1=mask, 2=Wq, 3=Wk, 4=Wv, 5=Wo, 6=S_q, 7=S_k
// ---------------------------------------------------------------------------
extern "C" void kernel_launch(void* const* d_in, const int* in_sizes, int n_in,
                              void* d_out, int out_size)
{
    const float* x  = (const float*)d_in[0];
    const float* Wq = (const float*)d_in[2];
    const float* Wk = (const float*)d_in[3];
    const float* Wv = (const float*)d_in[4];
    const float* Wo = (const float*)d_in[5];
    const float* Sq = (const float*)d_in[6];
    const float* Sk = (const float*)d_in[7];
    float* outp = (float*)d_out;

    float *dV;
    __nv_bfloat16 *dA2, *dO2, *dWQ2, *dWK2, *dWV2, *dWO2;
    cudaGetSymbolAddress((void**)&dV,   g_V);
    cudaGetSymbolAddress((void**)&dA2,  g_A2);
    cudaGetSymbolAddress((void**)&dO2,  g_O2);
    cudaGetSymbolAddress((void**)&dWQ2, g_WQ2);
    cudaGetSymbolAddress((void**)&dWK2, g_WK2);
    cudaGetSymbolAddress((void**)&dWV2, g_WV2);
    cudaGetSymbolAddress((void**)&dWO2, g_WO2);

    cudaFuncSetAttribute(gemm_mma2_kernel<0>, cudaFuncAttributeMaxDynamicSharedMemorySize, G2_SMEM);
    cudaFuncSetAttribute(gemm_mma2_kernel<1>, cudaFuncAttributeMaxDynamicSharedMemorySize, G2_SMEM);
    cudaFuncSetAttribute(gemm_mma2_kernel<2>, cudaFuncAttributeMaxDynamicSharedMemorySize, G2_SMEM);
    cudaFuncSetAttribute(attn_mma_kernel, cudaFuncAttributeMaxDynamicSharedMemorySize, AT_SMEM);

    // 1) fold S into projection weights + split (direct)
    weff_kernel<<<dim3(DD/256, HH, 2), 256>>>(Wq, Wk, Sq, Sk);

    // 2) bf16 hi/lo splits of x, Wv, Wo
    cvt_split_kernel<<<(MM*DD)/256, 256>>>(x,  dA2,  MM*DD);
    cvt_split_kernel<<<(DD*DD)/256, 256>>>(Wv, dWV2, DD*DD);
    cvt_split_kernel<<<(DD*DD)/256, 256>>>(Wo, dWO2, DD*DD);

    // 3) projections (HMMA, fused epilogues)
    const float qscale = 0.125f * 1.4426950408889634f;   // scale * log2(e)
    dim3 ggrid(DD/128, MM/128);   // (8, 32)
    gemm_mma2_kernel<1><<<ggrid, 256, G2_SMEM>>>(dA2, dWQ2, nullptr, qscale);  // -> g_Qs
    gemm_mma2_kernel<2><<<ggrid, 256, G2_SMEM>>>(dA2, dWK2, nullptr, 1.0f);    // -> g_Ks
    gemm_mma2_kernel<0><<<ggrid, 256, G2_SMEM>>>(dA2, dWV2, dV, 1.0f);         // -> g_V fp32

    // 4) V transpose to f16 hi/lo [d][s]
    cvt_vt_kernel<<<dim3(TT/64, BH), 256>>>(dV);

    // 5) flash attention (HMMA) -> g_O2 split directly
    attn_mma_kernel<<<dim3(TT/128, BH), 256, AT_SMEM>>>();

    // 6) output projection (HMMA) -> d_out fp32
    gemm_mma2_kernel<0><<<ggrid, 256, G2_SMEM>>>(dO2, dWO2, outp, 1.0f);
}

// round 8
// speedup vs baseline: 4.2351x; 1.0267x over previous
#include <cuda_runtime.h>
#include <cuda_bf16.h>
#include <cuda_fp16.h>
#include <math.h>
#include <stdint.h>

// Shapes (fixed)
#define BB 2
#define TT 2048
#define DD 1024
#define HH 16
#define DH 64
#define MM (BB*TT)   // 4096
#define BH (BB*HH)   // 32

// ---------------------------------------------------------------------------
// Scratch (no cudaMalloc allowed)
// ---------------------------------------------------------------------------
__device__ float g_V [MM*DD];                 // V projection (fp32, for transpose)
// bf16 hi/lo split GEMM operands: [rows][2048] = [hi(1024) | lo(1024)]
__device__ __nv_bfloat16 g_A2 [MM*2*DD];      // x split
__device__ __nv_bfloat16 g_O2 [MM*2*DD];      // attention output split (written by attn)
__device__ __nv_bfloat16 g_WQ2[DD*2*DD];      // folded Wq split (written by weff)
__device__ __nv_bfloat16 g_WK2[DD*2*DD];      // folded Wk split (written by weff)
__device__ __nv_bfloat16 g_WV2[DD*2*DD];
__device__ __nv_bfloat16 g_WO2[DD*2*DD];
// attention operands
__device__ __nv_bfloat16 g_Qs[BH*TT*128];     // [bh][t][hi64|lo64], Q pre-scaled
__device__ __nv_bfloat16 g_Ks[BH*TT*128];     // [bh][t][hi64|lo64]
__device__ __half        g_Vt[BH*2*DH*TT];    // [bh][hi/lo][d][s] (transposed)

// ---------------------------------------------------------------------------
// PTX helpers (sm_80-level only — ptxas targets plain sm_103, no tcgen05/TMA)
// ---------------------------------------------------------------------------
__device__ __forceinline__ uint32_t smem_u32(const void* p) {
    uint32_t a;
    asm("{ .reg .u64 t; cvta.to.shared.u64 t, %1; cvt.u32.u64 %0, t; }" : "=r"(a) : "l"(p));
    return a;
}
__device__ __forceinline__ void cp_async16(uint32_t dst, const void* src) {
    asm volatile("cp.async.cg.shared.global [%0], [%1], 16;\n" :: "r"(dst), "l"(src));
}
#define CP_COMMIT() asm volatile("cp.async.commit_group;\n" ::: "memory")
#define CP_WAIT1()  asm volatile("cp.async.wait_group 1;\n" ::: "memory")

__device__ __forceinline__ void ldsm4(uint32_t &r0, uint32_t &r1, uint32_t &r2, uint32_t &r3,
                                      uint32_t addr) {
    asm volatile("ldmatrix.sync.aligned.m8n8.x4.shared.b16 {%0,%1,%2,%3}, [%4];"
                 : "=r"(r0), "=r"(r1), "=r"(r2), "=r"(r3) : "r"(addr));
}
__device__ __forceinline__ void mma_bf16(float* c, const uint32_t* a, const uint32_t* b) {
    asm volatile("mma.sync.aligned.m16n8k16.row.col.f32.bf16.bf16.f32 "
                 "{%0,%1,%2,%3}, {%4,%5,%6,%7}, {%8,%9}, {%0,%1,%2,%3};"
                 : "+f"(c[0]), "+f"(c[1]), "+f"(c[2]), "+f"(c[3])
                 : "r"(a[0]), "r"(a[1]), "r"(a[2]), "r"(a[3]), "r"(b[0]), "r"(b[1]));
}
__device__ __forceinline__ void mma_f16(float* c, const uint32_t* a, const uint32_t* b) {
    asm volatile("mma.sync.aligned.m16n8k16.row.col.f32.f16.f16.f32 "
                 "{%0,%1,%2,%3}, {%4,%5,%6,%7}, {%8,%9}, {%0,%1,%2,%3};"
                 : "+f"(c[0]), "+f"(c[1]), "+f"(c[2]), "+f"(c[3])
                 : "r"(a[0]), "r"(a[1]), "r"(a[2]), "r"(a[3]), "r"(b[0]), "r"(b[1]));
}
__device__ __forceinline__ float ex2f(float x) {
    float r; asm("ex2.approx.ftz.f32 %0, %1;" : "=f"(r) : "f"(x)); return r;
}
__device__ __forceinline__ uint32_t ex2_h2(uint32_t x) {
    uint32_t r; asm("ex2.approx.f16x2 %0, %1;" : "=r"(r) : "r"(x)); return r;
}
__device__ __forceinline__ uint32_t f2h2u(float a, float b) {
    __half2 h = __floats2half2_rn(a, b);
    return *reinterpret_cast<uint32_t*>(&h);
}
__device__ __forceinline__ float2 h2u2f2(uint32_t u) {
    __half2 h = *reinterpret_cast<__half2*>(&u);
    return __half22float2(h);
}
__device__ __forceinline__ uint32_t pack_bf16(float a, float b) {
    __nv_bfloat162 h = __floats2bfloat162_rn(a, b);
    return *reinterpret_cast<uint32_t*>(&h);
}
__device__ __forceinline__ void split2(float v0, float v1, uint32_t &hi, uint32_t &lo) {
    __nv_bfloat16 h0 = __float2bfloat16(v0);
    __nv_bfloat16 h1 = __float2bfloat16(v1);
    float l0 = v0 - __bfloat162float(h0);
    float l1 = v1 - __bfloat162float(h1);
    uint32_t u0 = (uint32_t)*reinterpret_cast<uint16_t*>(&h0);
    uint32_t u1 = (uint32_t)*reinterpret_cast<uint16_t*>(&h1);
    hi = u0 | (u1 << 16);
    lo = pack_bf16(l0, l1);
}

// ---------------------------------------------------------------------------
// Weff fold + split (unchanged from R7)
// ---------------------------------------------------------------------------
__global__ __launch_bounds__(256)
void weff_kernel(const float* __restrict__ Wq, const float* __restrict__ Wk,
                 const float* __restrict__ Sq, const float* __restrict__ Sk)
{
    const int h = blockIdx.y;
    const bool isK = (blockIdx.z != 0);
    const float* __restrict__ W = isK ? Wk : Wq;
    const float* __restrict__ S = isK ? Sk : Sq;
    __nv_bfloat16* __restrict__ outp = isK ? g_WK2 : g_WQ2;

    __shared__ float s_s[DH*DH];
    for (int i = threadIdx.x; i < DH*DH; i += 256) s_s[i] = S[h*DH*DH + i];
    __syncthreads();

    const int d = blockIdx.x * 256 + threadIdx.x;
    float acc[DH];
#pragma unroll
    for (int e = 0; e < DH; e++) acc[e] = 0.f;
    for (int c = 0; c < DH; c++) {
        const float w = W[(h*DH + c)*DD + d];
#pragma unroll
        for (int e = 0; e < DH; e++) acc[e] += w * s_s[c*DH + e];
    }
#pragma unroll
    for (int e = 0; e < DH; e++) {
        float v = acc[e];
        __nv_bfloat16 hi = __float2bfloat16(v);
        float lo = v - __bfloat162float(hi);
        outp[(size_t)(h*DH + e)*2048 + d] = hi;
        outp[(size_t)(h*DH + e)*2048 + 1024 + d] = __float2bfloat16(lo);
    }
}

// ---------------------------------------------------------------------------
// fp32 -> bf16 hi/lo split (unchanged)
// ---------------------------------------------------------------------------
__global__ __launch_bounds__(256)
void cvt_split_kernel(const float* __restrict__ src, __nv_bfloat16* __restrict__ dst, int n)
{
    int i = blockIdx.x * 256 + threadIdx.x;
    if (i >= n) return;
    int r = i >> 10, c = i & 1023;
    float v = src[i];
    __nv_bfloat16 hi = __float2bfloat16(v);
    float lof = v - __bfloat162float(hi);
    dst[(size_t)r*2048 + c] = hi;
    dst[(size_t)r*2048 + 1024 + c] = __float2bfloat16(lof);
}

// ---------------------------------------------------------------------------
// V transpose + f16 hi/lo (unchanged)
// ---------------------------------------------------------------------------
__global__ __launch_bounds__(256)
void cvt_vt_kernel(const float* __restrict__ V)
{
    __shared__ float tile[64][65];
    const int bh = blockIdx.y;
    const int b = bh >> 4, h = bh & 15;
    const int s0 = blockIdx.x * 64;

    for (int i = threadIdx.x; i < 64*64; i += 256) {
        int si = i >> 6, d = i & 63;
        tile[si][d] = V[((size_t)(b*TT + s0 + si))*DD + h*DH + d];
    }
    __syncthreads();
    __half* dh = g_Vt + ((size_t)(bh*2    ) * DH) * TT;
    __half* dl = g_Vt + ((size_t)(bh*2 + 1) * DH) * TT;
    for (int i = threadIdx.x; i < 64*64; i += 256) {
        int d = i >> 6, s = i & 63;
        float v = tile[s][d];
        __half hi = __float2half_rn(v);
        __half lo = __float2half_rn(v - __half2float(hi));
        dh[(size_t)d*TT + s0 + s] = hi;
        dl[(size_t)d*TT + s0 + s] = lo;
    }
}

// ---------------------------------------------------------------------------
// HMMA NT GEMM, merged hi/lo (unchanged from R7 — at HMMA issue floor)
// ---------------------------------------------------------------------------
#define G2_TILE  (128*144)
#define G2_STAGE (4*G2_TILE)
#define G2_SMEM  (2*G2_STAGE)

template<int MODE>
__global__ __launch_bounds__(256, 1)
void gemm_mma2_kernel(const __nv_bfloat16* __restrict__ A2,
                      const __nv_bfloat16* __restrict__ B2,
                      float* __restrict__ C, float scale)
{
    extern __shared__ char smraw[];
    const uint32_t sbase = smem_u32(smraw);
    const int tid = threadIdx.x;
    const int wid = tid >> 5, lane = tid & 31;
    const int warp_m = wid >> 1, warp_n = wid & 1;
    const int m0 = blockIdx.y * 128, n0 = blockIdx.x * 128;

    float acc[2][8][4];
#pragma unroll
    for (int a = 0; a < 2; a++)
#pragma unroll
        for (int b = 0; b < 8; b++)
#pragma unroll
            for (int c = 0; c < 4; c++) acc[a][b][c] = 0.f;

    auto LOAD = [&](int it) {
        const uint32_t st = sbase + (it & 1) * G2_STAGE;
        const char* gAh = (const char*)(A2 + (size_t)m0*2048 + it*64);
        const char* gBh = (const char*)(B2 + (size_t)n0*2048 + it*64);
#pragma unroll
        for (int i = 0; i < 4; i++) {
            int u = tid + i*256;
            int row = u >> 3, kb = (u & 7) << 4;
            const size_t go = (size_t)row*4096 + kb;
            const uint32_t so = row*144 + kb;
            cp_async16(st             + so, gAh + go);
            cp_async16(st +   G2_TILE + so, gAh + 2048 + go);
            cp_async16(st + 2*G2_TILE + so, gBh + go);
            cp_async16(st + 3*G2_TILE + so, gBh + 2048 + go);
        }
    };

    LOAD(0); CP_COMMIT();
    LOAD(1); CP_COMMIT();

    const int NIT = 16;
    for (int it = 0; it < NIT; it++) {
        CP_WAIT1();
        __syncthreads();
        const uint32_t st = sbase + (it & 1) * G2_STAGE;
#pragma unroll
        for (int j = 0; j < 4; j++) {
            const uint32_t cb = j*32 + ((lane >> 4) << 4);
            uint32_t ah[2][4], al[2][4];
#pragma unroll
            for (int mf = 0; mf < 2; mf++) {
                const uint32_t ro = (warp_m*32 + mf*16 + (lane & 15))*144 + cb;
                ldsm4(ah[mf][0], ah[mf][1], ah[mf][2], ah[mf][3], st + ro);
                ldsm4(al[mf][0], al[mf][1], al[mf][2], al[mf][3], st + G2_TILE + ro);
            }
            uint32_t bh[8][2], bl[8][2];
#pragma unroll
            for (int nf2 = 0; nf2 < 4; nf2++) {
                const uint32_t ro = (warp_n*64 + nf2*16 + (lane & 15))*144 + cb;
                uint32_t r0, r1, r2, r3;
                ldsm4(r0, r1, r2, r3, st + 2*G2_TILE + ro);
                bh[nf2*2][0] = r0; bh[nf2*2][1] = r2;
                bh[nf2*2+1][0] = r1; bh[nf2*2+1][1] = r3;
                ldsm4(r0, r1, r2, r3, st + 3*G2_TILE + ro);
                bl[nf2*2][0] = r0; bl[nf2*2][1] = r2;
                bl[nf2*2+1][0] = r1; bl[nf2*2+1][1] = r3;
            }
#pragma unroll
            for (int mf = 0; mf < 2; mf++)
#pragma unroll
                for (int nf = 0; nf < 8; nf++) {
                    mma_bf16(acc[mf][nf], ah[mf], bh[nf]);
                    mma_bf16(acc[mf][nf], ah[mf], bl[nf]);
                    mma_bf16(acc[mf][nf], al[mf], bh[nf]);
                }
        }
        __syncthreads();
        if (it + 2 < NIT) LOAD(it + 2);
        CP_COMMIT();
    }

    const int g = lane >> 2, t = lane & 3;
#pragma unroll
    for (int mf = 0; mf < 2; mf++) {
        const int row0 = m0 + warp_m*32 + mf*16 + g;
#pragma unroll
        for (int nf = 0; nf < 8; nf++) {
            const int col = n0 + warp_n*64 + nf*8 + t*2;
            if (MODE == 0) {
                *(float2*)&C[(size_t)row0*DD + col]     = make_float2(acc[mf][nf][0], acc[mf][nf][1]);
                *(float2*)&C[(size_t)(row0+8)*DD + col] = make_float2(acc[mf][nf][2], acc[mf][nf][3]);
            } else {
                __nv_bfloat16* dst = (MODE == 1) ? g_Qs : g_Ks;
                const int h = col >> 6, e = col & 63;
#pragma unroll
                for (int rr = 0; rr < 2; rr++) {
                    const int row = row0 + rr*8;
                    const int b = row >> 11, tq = row & 2047;
                    const size_t base = ((size_t)(b*HH + h)*TT + tq) << 7;
                    uint32_t hi, lo;
                    split2(acc[mf][nf][rr*2] * scale, acc[mf][nf][rr*2+1] * scale, hi, lo);
                    *(uint32_t*)&dst[base + e]      = hi;
                    *(uint32_t*)&dst[base + 64 + e] = lo;
                }
            }
        }
    }
}

// ---------------------------------------------------------------------------
// Flash attention on HMMA — 128-key chunks (16 chunks instead of 32).
// Halves per-chunk fixed costs: shfl chains, corr/ex2, of-rescale, syncs.
// ---------------------------------------------------------------------------
#define AT_QSTRIDE 272
#define AT_QBYTES  (128*272)            // 34816
#define AT_KARR    (128*144)            // 18432 (Khi / Klo)
#define AT_VARR    (64*272)             // 17408 (Vhi / Vlo; 64 d-rows x 256B)
#define AT_STAGE   (2*AT_KARR + 2*AT_VARR)  // 71680
#define AT_SMEM    (AT_QBYTES + 2*AT_STAGE) // 178176

__global__ __launch_bounds__(256, 1)
void attn_mma_kernel()
{
    extern __shared__ char smraw[];
    const uint32_t sbase = smem_u32(smraw);
    const int tid = threadIdx.x, wid = tid >> 5, lane = tid & 31;
    const int bh = blockIdx.y;
    const int q0 = blockIdx.x * 128;

    const char* Qbase = (const char*)(g_Qs + ((size_t)bh*TT + q0) * 128);
    const char* Kbase = (const char*)(g_Ks + (size_t)bh*TT*128);
    const char* Vh    = (const char*)(g_Vt + ((size_t)(bh*2    )*DH)*TT);
    const char* Vl    = (const char*)(g_Vt + ((size_t)(bh*2 + 1)*DH)*TT);

    // Q tile -> smem
#pragma unroll
    for (int i = 0; i < 8; i++) {
        int u = tid + i*256;
        int row = u >> 4, cb = (u & 15) << 4;
        cp_async16(sbase + row*AT_QSTRIDE + cb, Qbase + (size_t)row*256 + cb);
    }
    CP_COMMIT();

    auto LOADC = [&](int c) {
        const uint32_t s = sbase + AT_QBYTES + (c & 1) * AT_STAGE;
        const char* ksrc = Kbase + (size_t)c*128*256;
        const char* vhs  = Vh + (size_t)c*256;      // 128 s-cols x 2B
        const char* vls  = Vl + (size_t)c*256;
        // K: 128 rows x 256B (hi|lo interleaved in source row)
#pragma unroll
        for (int i = 0; i < 4; i++) {
            int u = tid + i*256;                    // 0..1023
            int r = u >> 3, kb = (u & 7) << 4;
            cp_async16(s           + r*144 + kb, ksrc + (size_t)r*256 + kb);
            cp_async16(s + AT_KARR + r*144 + kb, ksrc + (size_t)r*256 + 128 + kb);
        }
        // V: 64 d-rows x 256B
#pragma unroll
        for (int i = 0; i < 4; i++) {
            int u = tid + i*256;                    // 0..1023
            int r = u >> 4, kb = (u & 15) << 4;
            cp_async16(s + 2*AT_KARR           + r*272 + kb, vhs + (size_t)r*4096 + kb);
            cp_async16(s + 2*AT_KARR + AT_VARR + r*272 + kb, vls + (size_t)r*4096 + kb);
        }
    };

    LOADC(0); CP_COMMIT();
    CP_WAIT1();
    __syncthreads();

    // Q fragments
    uint32_t qh[4][4], ql[4][4];
#pragma unroll
    for (int j = 0; j < 4; j++) {
        uint32_t base = sbase + (wid*16 + (lane & 15))*AT_QSTRIDE + j*32 + ((lane >> 4) << 4);
        ldsm4(qh[j][0], qh[j][1], qh[j][2], qh[j][3], base);
        ldsm4(ql[j][0], ql[j][1], ql[j][2], ql[j][3], base + 128);
    }

    float of[8][4];
#pragma unroll
    for (int f = 0; f < 8; f++)
#pragma unroll
        for (int c = 0; c < 4; c++) of[f][c] = 0.f;
    float m0 = -1e30f, m1 = -1e30f, l0 = 0.f, l1 = 0.f;

    for (int c = 0; c < 16; c++) {
        if (c + 1 < 16) LOADC(c + 1);
        CP_COMMIT();
        CP_WAIT1();
        __syncthreads();

        const uint32_t sK  = sbase + AT_QBYTES + (c & 1) * AT_STAGE;
        const uint32_t sKl = sK + AT_KARR;
        const uint32_t sVh = sK + 2*AT_KARR;
        const uint32_t sVl = sVh + AT_VARR;

        // ---- scores: 128 keys = 16 n-fragments ----
        float sfr[16][4];
#pragma unroll
        for (int f = 0; f < 16; f++)
#pragma unroll
            for (int r = 0; r < 4; r++) sfr[f][r] = 0.f;

#pragma unroll
        for (int j = 0; j < 4; j++) {
            const uint32_t cb = j*32 + ((lane >> 4) << 4);
#pragma unroll
            for (int nf2 = 0; nf2 < 8; nf2++) {     // K hi: 3-term needs qh+ql
                uint32_t r0, r1, r2, r3;
                ldsm4(r0, r1, r2, r3, sK + (nf2*16 + (lane & 15))*144 + cb);
                uint32_t b0[2] = {r0, r2}, b1[2] = {r1, r3};
                mma_bf16(sfr[2*nf2  ], qh[j], b0);
                mma_bf16(sfr[2*nf2  ], ql[j], b0);
                mma_bf16(sfr[2*nf2+1], qh[j], b1);
                mma_bf16(sfr[2*nf2+1], ql[j], b1);
            }
#pragma unroll
            for (int nf2 = 0; nf2 < 8; nf2++) {     // K lo: qh only
                uint32_t r0, r1, r2, r3;
                ldsm4(r0, r1, r2, r3, sKl + (nf2*16 + (lane & 15))*144 + cb);
                uint32_t b0[2] = {r0, r2}, b1[2] = {r1, r3};
                mma_bf16(sfr[2*nf2  ], qh[j], b0);
                mma_bf16(sfr[2*nf2+1], qh[j], b1);
            }
        }

        // ---- online softmax (exp2 domain) ----
        float mx0 = sfr[0][0], mx1 = sfr[0][2];
#pragma unroll
        for (int f = 0; f < 16; f++) {
            mx0 = fmaxf(mx0, fmaxf(sfr[f][0], sfr[f][1]));
            mx1 = fmaxf(mx1, fmaxf(sfr[f][2], sfr[f][3]));
        }
        mx0 = fmaxf(mx0, __shfl_xor_sync(0xffffffffu, mx0, 1));
        mx0 = fmaxf(mx0, __shfl_xor_sync(0xffffffffu, mx0, 2));
        mx1 = fmaxf(mx1, __shfl_xor_sync(0xffffffffu, mx1, 1));
        mx1 = fmaxf(mx1, __shfl_xor_sync(0xffffffffu, mx1, 2));
        const float m0n = fmaxf(m0, mx0), m1n = fmaxf(m1, mx1);
        const float corr0 = ex2f(m0 - m0n), corr1 = ex2f(m1 - m1n);

        uint32_t pa[8][4];
        float l0a = 0.f, l1a = 0.f;
#pragma unroll
        for (int f = 0; f < 16; f++) {
            uint32_t p01 = ex2_h2(f2h2u(sfr[f][0] - m0n, sfr[f][1] - m0n));
            uint32_t p23 = ex2_h2(f2h2u(sfr[f][2] - m1n, sfr[f][3] - m1n));
            const int j = f >> 1;
            if (f & 1) { pa[j][2] = p01; pa[j][3] = p23; }
            else       { pa[j][0] = p01; pa[j][1] = p23; }
            float2 a = h2u2f2(p01); l0a += a.x + a.y;
            float2 bs = h2u2f2(p23); l1a += bs.x + bs.y;
        }
        l0a += __shfl_xor_sync(0xffffffffu, l0a, 1);
        l0a += __shfl_xor_sync(0xffffffffu, l0a, 2);
        l1a += __shfl_xor_sync(0xffffffffu, l1a, 1);
        l1a += __shfl_xor_sync(0xffffffffu, l1a, 2);
        l0 = l0 * corr0 + l0a;
        l1 = l1 * corr1 + l1a;
        m0 = m0n; m1 = m1n;

#pragma unroll
        for (int f = 0; f < 8; f++) {
            of[f][0] *= corr0; of[f][1] *= corr0;
            of[f][2] *= corr1; of[f][3] *= corr1;
        }

        // ---- PV (f16): O += P*Vhi + P*Vlo over 8 k-fragments ----
#pragma unroll
        for (int j = 0; j < 8; j++) {
            const uint32_t cb = j*32 + ((lane >> 4) << 4);
#pragma unroll
            for (int nf2 = 0; nf2 < 4; nf2++) {
                uint32_t r0, r1, r2, r3;
                ldsm4(r0, r1, r2, r3, sVh + (nf2*16 + (lane & 15))*272 + cb);
                uint32_t b0[2] = {r0, r2}, b1[2] = {r1, r3};
                mma_f16(of[2*nf2  ], pa[j], b0);
                mma_f16(of[2*nf2+1], pa[j], b1);
            }
#pragma unroll
            for (int nf2 = 0; nf2 < 4; nf2++) {
                uint32_t r0, r1, r2, r3;
                ldsm4(r0, r1, r2, r3, sVl + (nf2*16 + (lane & 15))*272 + cb);
                uint32_t b0[2] = {r0, r2}, b1[2] = {r1, r3};
                mma_f16(of[2*nf2  ], pa[j], b0);
                mma_f16(of[2*nf2+1], pa[j], b1);
            }
        }
        __syncthreads();
    }

    // epilogue: write split O directly to g_O2 [row][2048]
    const float inv0 = 1.f / l0, inv1 = 1.f / l1;
    const int b = bh >> 4, h = bh & 15;
    const int g = lane >> 2, t = lane & 3;
    const int qrow = q0 + wid*16 + g;
#pragma unroll
    for (int f = 0; f < 8; f++) {
        const int col = h*DH + f*8 + t*2;
#pragma unroll
        for (int rr = 0; rr < 2; rr++) {
            const size_t row = (size_t)(b*TT) + qrow + rr*8;
            const float inv = rr ? inv1 : inv0;
            uint32_t hi, lo;
            split2(of[f][rr*2] * inv, of[f][rr*2+1] * inv, hi, lo);
            *(uint32_t*)&g_O2[row*2048 + col]        = hi;
            *(uint32_t*)&g_O2[row*2048 + 1024 + col] = lo;
        }
    }
}

// ---------------------------------------------------------------------------
// Launch. Inputs: 0=x, 1=mask, 2=Wq, 3=Wk, 4=Wv, 5=Wo, 6=S_q, 7=S_k
// ---------------------------------------------------------------------------
extern "C" void kernel_launch(void* const* d_in, const int* in_sizes, int n_in,
                              void* d_out, int out_size)
{
    const float* x  = (const float*)d_in[0];
    const float* Wq = (const float*)d_in[2];
    const float* Wk = (const float*)d_in[3];
    const float* Wv = (const float*)d_in[4];
    const float* Wo = (const float*)d_in[5];
    const float* Sq = (const float*)d_in[6];
    const float* Sk = (const float*)d_in[7];
    float* outp = (float*)d_out;

    float *dV;
    __nv_bfloat16 *dA2, *dO2, *dWQ2, *dWK2, *dWV2, *dWO2;
    cudaGetSymbolAddress((void**)&dV,   g_V);
    cudaGetSymbolAddress((void**)&dA2,  g_A2);
    cudaGetSymbolAddress((void**)&dO2,  g_O2);
    cudaGetSymbolAddress((void**)&dWQ2, g_WQ2);
    cudaGetSymbolAddress((void**)&dWK2, g_WK2);
    cudaGetSymbolAddress((void**)&dWV2, g_WV2);
    cudaGetSymbolAddress((void**)&dWO2, g_WO2);

    cudaFuncSetAttribute(gemm_mma2_kernel<0>, cudaFuncAttributeMaxDynamicSharedMemorySize, G2_SMEM);
    cudaFuncSetAttribute(gemm_mma2_kernel<1>, cudaFuncAttributeMaxDynamicSharedMemorySize, G2_SMEM);
    cudaFuncSetAttribute(gemm_mma2_kernel<2>, cudaFuncAttributeMaxDynamicSharedMemorySize, G2_SMEM);
    cudaFuncSetAttribute(attn_mma_kernel, cudaFuncAttributeMaxDynamicSharedMemorySize, AT_SMEM);

    // 1) fold S into projection weights + split (direct)
    weff_kernel<<<dim3(DD/256, HH, 2), 256>>>(Wq, Wk, Sq, Sk);

    // 2) bf16 hi/lo splits of x, Wv, Wo
    cvt_split_kernel<<<(MM*DD)/256, 256>>>(x,  dA2,  MM*DD);
    cvt_split_kernel<<<(DD*DD)/256, 256>>>(Wv, dWV2, DD*DD);
    cvt_split_kernel<<<(DD*DD)/256, 256>>>(Wo, dWO2, DD*DD);

    // 3) projections (HMMA, fused epilogues)
    const float qscale = 0.125f * 1.4426950408889634f;   // scale * log2(e)
    dim3 ggrid(DD/128, MM/128);   // (8, 32)
    gemm_mma2_kernel<1><<<ggrid, 256, G2_SMEM>>>(dA2, dWQ2, nullptr, qscale);  // -> g_Qs
    gemm_mma2_kernel<2><<<ggrid, 256, G2_SMEM>>>(dA2, dWK2, nullptr, 1.0f);    // -> g_Ks
    gemm_mma2_kernel<0><<<ggrid, 256, G2_SMEM>>>(dA2, dWV2, dV, 1.0f);         // -> g_V fp32

    // 4) V transpose to f16 hi/lo [d][s]
    cvt_vt_kernel<<<dim3(TT/64, BH), 256>>>(dV);

    // 5) flash attention (HMMA, 128-key chunks) -> g_O2 split directly
    attn_mma_kernel<<<dim3(TT/128, BH), 256, AT_SMEM>>>();

    // 6) output projection (HMMA) -> d_out fp32
    gemm_mma2_kernel<0><<<ggrid, 256, G2_SMEM>>>(dO2, dWO2, outp, 1.0f);
}

// round 9
// speedup vs baseline: 4.7646x; 1.1250x over previous
#include <cuda_runtime.h>
#include <cuda_bf16.h>
#include <cuda_fp16.h>
#include <math.h>
#include <stdint.h>

// Shapes (fixed)
#define BB 2
#define TT 2048
#define DD 1024
#define HH 16
#define DH 64
#define MM (BB*TT)   // 4096
#define BH (BB*HH)   // 32

// ---------------------------------------------------------------------------
// Scratch (no cudaMalloc allowed)
// ---------------------------------------------------------------------------
__device__ __nv_bfloat16 g_A2 [MM*2*DD];      // x split [rows][hi1024|lo1024]
__device__ __nv_bfloat16 g_O2 [MM*2*DD];      // attention output split
__device__ __nv_bfloat16 g_WQ2[DD*2*DD];      // folded Wq split
__device__ __nv_bfloat16 g_WK2[DD*2*DD];      // folded Wk split
__device__ __nv_bfloat16 g_WV2[DD*2*DD];
__device__ __nv_bfloat16 g_WO2[DD*2*DD];
__device__ __nv_bfloat16 g_Qs[BH*TT*128];     // [bh][t][hi64|lo64], Q pre-scaled
__device__ __nv_bfloat16 g_Ks[BH*TT*128];     // [bh][t][hi64|lo64]
__device__ __half        g_Vt[BH*DH*TT];      // [bh][d][s]  (f16, transposed)

// ---------------------------------------------------------------------------
// PTX helpers (sm_80-level only — ptxas targets plain sm_103, no tcgen05/TMA)
// ---------------------------------------------------------------------------
__device__ __forceinline__ uint32_t smem_u32(const void* p) {
    uint32_t a;
    asm("{ .reg .u64 t; cvta.to.shared.u64 t, %1; cvt.u32.u64 %0, t; }" : "=r"(a) : "l"(p));
    return a;
}
__device__ __forceinline__ void cp_async16(uint32_t dst, const void* src) {
    asm volatile("cp.async.cg.shared.global [%0], [%1], 16;\n" :: "r"(dst), "l"(src));
}
#define CP_COMMIT() asm volatile("cp.async.commit_group;\n" ::: "memory")
#define CP_WAIT1()  asm volatile("cp.async.wait_group 1;\n" ::: "memory")

__device__ __forceinline__ void ldsm4(uint32_t &r0, uint32_t &r1, uint32_t &r2, uint32_t &r3,
                                      uint32_t addr) {
    asm volatile("ldmatrix.sync.aligned.m8n8.x4.shared.b16 {%0,%1,%2,%3}, [%4];"
                 : "=r"(r0), "=r"(r1), "=r"(r2), "=r"(r3) : "r"(addr));
}
__device__ __forceinline__ void mma_bf16(float* c, const uint32_t* a, const uint32_t* b) {
    asm volatile("mma.sync.aligned.m16n8k16.row.col.f32.bf16.bf16.f32 "
                 "{%0,%1,%2,%3}, {%4,%5,%6,%7}, {%8,%9}, {%0,%1,%2,%3};"
                 : "+f"(c[0]), "+f"(c[1]), "+f"(c[2]), "+f"(c[3])
                 : "r"(a[0]), "r"(a[1]), "r"(a[2]), "r"(a[3]), "r"(b[0]), "r"(b[1]));
}
__device__ __forceinline__ void mma_f16(float* c, const uint32_t* a, const uint32_t* b) {
    asm volatile("mma.sync.aligned.m16n8k16.row.col.f32.f16.f16.f32 "
                 "{%0,%1,%2,%3}, {%4,%5,%6,%7}, {%8,%9}, {%0,%1,%2,%3};"
                 : "+f"(c[0]), "+f"(c[1]), "+f"(c[2]), "+f"(c[3])
                 : "r"(a[0]), "r"(a[1]), "r"(a[2]), "r"(a[3]), "r"(b[0]), "r"(b[1]));
}
__device__ __forceinline__ float ex2f(float x) {
    float r; asm("ex2.approx.ftz.f32 %0, %1;" : "=f"(r) : "f"(x)); return r;
}
__device__ __forceinline__ uint32_t ex2_h2(uint32_t x) {
    uint32_t r; asm("ex2.approx.f16x2 %0, %1;" : "=r"(r) : "r"(x)); return r;
}
__device__ __forceinline__ uint32_t f2h2u(float a, float b) {
    __half2 h = __floats2half2_rn(a, b);
    return *reinterpret_cast<uint32_t*>(&h);
}
__device__ __forceinline__ float2 h2u2f2(uint32_t u) {
    __half2 h = *reinterpret_cast<__half2*>(&u);
    return __half22float2(h);
}
__device__ __forceinline__ uint32_t pack_bf16(float a, float b) {
    __nv_bfloat162 h = __floats2bfloat162_rn(a, b);
    return *reinterpret_cast<uint32_t*>(&h);
}
__device__ __forceinline__ void split2(float v0, float v1, uint32_t &hi, uint32_t &lo) {
    __nv_bfloat16 h0 = __float2bfloat16(v0);
    __nv_bfloat16 h1 = __float2bfloat16(v1);
    float l0 = v0 - __bfloat162float(h0);
    float l1 = v1 - __bfloat162float(h1);
    uint32_t u0 = (uint32_t)*reinterpret_cast<uint16_t*>(&h0);
    uint32_t u1 = (uint32_t)*reinterpret_cast<uint16_t*>(&h1);
    hi = u0 | (u1 << 16);
    lo = pack_bf16(l0, l1);
}

// ---------------------------------------------------------------------------
// weff_all: z=0/1 fold+split Wq/Wk with S; z=2/3 plain split of Wv/Wo.
// grid (DD/256, HH, 4), 256 threads.
// ---------------------------------------------------------------------------
__global__ __launch_bounds__(256)
void weff_all_kernel(const float* __restrict__ Wq, const float* __restrict__ Wk,
                     const float* __restrict__ Wv, const float* __restrict__ Wo,
                     const float* __restrict__ Sq, const float* __restrict__ Sk)
{
    const int h = blockIdx.y;
    const int z = blockIdx.z;
    const int d = blockIdx.x * 256 + threadIdx.x;

    if (z < 2) {
        const float* __restrict__ W = z ? Wk : Wq;
        const float* __restrict__ S = z ? Sk : Sq;
        __nv_bfloat16* __restrict__ outp = z ? g_WK2 : g_WQ2;

        __shared__ float s_s[DH*DH];
        for (int i = threadIdx.x; i < DH*DH; i += 256) s_s[i] = S[h*DH*DH + i];
        __syncthreads();

        float acc[DH];
#pragma unroll
        for (int e = 0; e < DH; e++) acc[e] = 0.f;
        for (int c = 0; c < DH; c++) {
            const float w = W[(h*DH + c)*DD + d];
#pragma unroll
            for (int e = 0; e < DH; e++) acc[e] += w * s_s[c*DH + e];
        }
#pragma unroll
        for (int e = 0; e < DH; e++) {
            float v = acc[e];
            __nv_bfloat16 hi = __float2bfloat16(v);
            float lo = v - __bfloat162float(hi);
            outp[(size_t)(h*DH + e)*2048 + d] = hi;
            outp[(size_t)(h*DH + e)*2048 + 1024 + d] = __float2bfloat16(lo);
        }
    } else {
        const float* __restrict__ W = (z == 2) ? Wv : Wo;
        __nv_bfloat16* __restrict__ outp = (z == 2) ? g_WV2 : g_WO2;
        for (int c = 0; c < DH; c++) {
            const int row = h*DH + c;
            float v = W[(size_t)row*DD + d];
            __nv_bfloat16 hi = __float2bfloat16(v);
            float lo = v - __bfloat162float(hi);
            outp[(size_t)row*2048 + d] = hi;
            outp[(size_t)row*2048 + 1024 + d] = __float2bfloat16(lo);
        }
    }
}

// ---------------------------------------------------------------------------
// fp32 -> bf16 hi/lo split (x only)
// ---------------------------------------------------------------------------
__global__ __launch_bounds__(256)
void cvt_split_kernel(const float* __restrict__ src, __nv_bfloat16* __restrict__ dst, int n)
{
    int i = blockIdx.x * 256 + threadIdx.x;
    if (i >= n) return;
    int r = i >> 10, c = i & 1023;
    float v = src[i];
    __nv_bfloat16 hi = __float2bfloat16(v);
    float lof = v - __bfloat162float(hi);
    dst[(size_t)r*2048 + c] = hi;
    dst[(size_t)r*2048 + 1024 + c] = __float2bfloat16(lof);
}

// ---------------------------------------------------------------------------
// Merged QKV GEMM: grid (24, 32).  n-superblock 0-7 -> Q, 8-15 -> K, 16-23 -> V.
// Same HMMA mainloop as R8; epilogue routes per superblock:
//   Q -> g_Qs (scaled, split, attn layout), K -> g_Ks, V -> g_Vt f16 [bh][d][s].
// Also used with ROUTE=3 (plain fp32 C) for the output projection.
// ---------------------------------------------------------------------------
#define G2_TILE  (128*144)
#define G2_STAGE (4*G2_TILE)
#define G2_SMEM  (2*G2_STAGE)

template<int QKV>
__global__ __launch_bounds__(256, 1)
void gemm_mma2_kernel(const __nv_bfloat16* __restrict__ A2,
                      const __nv_bfloat16* __restrict__ Bq,
                      const __nv_bfloat16* __restrict__ Bk,
                      const __nv_bfloat16* __restrict__ Bv,
                      float* __restrict__ C, float qscale)
{
    extern __shared__ char smraw[];
    const uint32_t sbase = smem_u32(smraw);
    const int tid = threadIdx.x;
    const int wid = tid >> 5, lane = tid & 31;
    const int warp_m = wid >> 1, warp_n = wid & 1;
    const int m0 = blockIdx.y * 128;
    const int nb = QKV ? (blockIdx.x >> 3) : 0;         // 0=Q,1=K,2=V
    const int n0 = QKV ? ((blockIdx.x & 7) * 128) : (blockIdx.x * 128);
    const __nv_bfloat16* __restrict__ B2 =
        QKV ? ((nb == 0) ? Bq : (nb == 1) ? Bk : Bv) : Bq;

    float acc[2][8][4];
#pragma unroll
    for (int a = 0; a < 2; a++)
#pragma unroll
        for (int b = 0; b < 8; b++)
#pragma unroll
            for (int c = 0; c < 4; c++) acc[a][b][c] = 0.f;

    auto LOAD = [&](int it) {
        const uint32_t st = sbase + (it & 1) * G2_STAGE;
        const char* gAh = (const char*)(A2 + (size_t)m0*2048 + it*64);
        const char* gBh = (const char*)(B2 + (size_t)n0*2048 + it*64);
#pragma unroll
        for (int i = 0; i < 4; i++) {
            int u = tid + i*256;
            int row = u >> 3, kb = (u & 7) << 4;
            const size_t go = (size_t)row*4096 + kb;
            const uint32_t so = row*144 + kb;
            cp_async16(st             + so, gAh + go);
            cp_async16(st +   G2_TILE + so, gAh + 2048 + go);
            cp_async16(st + 2*G2_TILE + so, gBh + go);
            cp_async16(st + 3*G2_TILE + so, gBh + 2048 + go);
        }
    };

    LOAD(0); CP_COMMIT();
    LOAD(1); CP_COMMIT();

    const int NIT = 16;
    for (int it = 0; it < NIT; it++) {
        CP_WAIT1();
        __syncthreads();
        const uint32_t st = sbase + (it & 1) * G2_STAGE;
#pragma unroll
        for (int j = 0; j < 4; j++) {
            const uint32_t cb = j*32 + ((lane >> 4) << 4);
            uint32_t ah[2][4], al[2][4];
#pragma unroll
            for (int mf = 0; mf < 2; mf++) {
                const uint32_t ro = (warp_m*32 + mf*16 + (lane & 15))*144 + cb;
                ldsm4(ah[mf][0], ah[mf][1], ah[mf][2], ah[mf][3], st + ro);
                ldsm4(al[mf][0], al[mf][1], al[mf][2], al[mf][3], st + G2_TILE + ro);
            }
            uint32_t bh[8][2], bl[8][2];
#pragma unroll
            for (int nf2 = 0; nf2 < 4; nf2++) {
                const uint32_t ro = (warp_n*64 + nf2*16 + (lane & 15))*144 + cb;
                uint32_t r0, r1, r2, r3;
                ldsm4(r0, r1, r2, r3, st + 2*G2_TILE + ro);
                bh[nf2*2][0] = r0; bh[nf2*2][1] = r2;
                bh[nf2*2+1][0] = r1; bh[nf2*2+1][1] = r3;
                ldsm4(r0, r1, r2, r3, st + 3*G2_TILE + ro);
                bl[nf2*2][0] = r0; bl[nf2*2][1] = r2;
                bl[nf2*2+1][0] = r1; bl[nf2*2+1][1] = r3;
            }
#pragma unroll
            for (int mf = 0; mf < 2; mf++)
#pragma unroll
                for (int nf = 0; nf < 8; nf++) {
                    mma_bf16(acc[mf][nf], ah[mf], bh[nf]);
                    mma_bf16(acc[mf][nf], ah[mf], bl[nf]);
                    mma_bf16(acc[mf][nf], al[mf], bh[nf]);
                }
        }
        __syncthreads();
        if (it + 2 < NIT) LOAD(it + 2);
        CP_COMMIT();
    }

    const int g = lane >> 2, t = lane & 3;
#pragma unroll
    for (int mf = 0; mf < 2; mf++) {
        const int row0 = m0 + warp_m*32 + mf*16 + g;
#pragma unroll
        for (int nf = 0; nf < 8; nf++) {
            const int col = n0 + warp_n*64 + nf*8 + t*2;
            if (!QKV) {
                *(float2*)&C[(size_t)row0*DD + col]     = make_float2(acc[mf][nf][0], acc[mf][nf][1]);
                *(float2*)&C[(size_t)(row0+8)*DD + col] = make_float2(acc[mf][nf][2], acc[mf][nf][3]);
            } else if (nb < 2) {
                __nv_bfloat16* dst = (nb == 0) ? g_Qs : g_Ks;
                const float sc = (nb == 0) ? qscale : 1.0f;
                const int h = col >> 6, e = col & 63;
#pragma unroll
                for (int rr = 0; rr < 2; rr++) {
                    const int row = row0 + rr*8;
                    const int b = row >> 11, tq = row & 2047;
                    const size_t base = ((size_t)(b*HH + h)*TT + tq) << 7;
                    uint32_t hi, lo;
                    split2(acc[mf][nf][rr*2] * sc, acc[mf][nf][rr*2+1] * sc, hi, lo);
                    *(uint32_t*)&dst[base + e]      = hi;
                    *(uint32_t*)&dst[base + 64 + e] = lo;
                }
            } else {
                // V -> g_Vt f16 [bh][d][s]
                const int h = col >> 6, dbase = col & 63;
#pragma unroll
                for (int rr = 0; rr < 2; rr++) {
                    const int row = row0 + rr*8;
                    const int b = row >> 11, tq = row & 2047;
                    const int bh = b*HH + h;
#pragma unroll
                    for (int cc = 0; cc < 2; cc++) {
                        const int d = dbase + cc;
                        g_Vt[((size_t)bh*DH + d)*TT + tq] =
                            __float2half_rn(acc[mf][nf][rr*2 + cc]);
                    }
                }
            }
        }
    }
}

// ---------------------------------------------------------------------------
// Flash attention on HMMA — 128-key chunks, single-f16 V.
// ---------------------------------------------------------------------------
#define AT_QSTRIDE 272
#define AT_QBYTES  (128*272)            // 34816
#define AT_KARR    (128*144)            // 18432 (Khi / Klo)
#define AT_VARR    (64*272)             // 17408 (V f16; 64 d-rows x 256B)
#define AT_STAGE   (2*AT_KARR + AT_VARR)    // 54272
#define AT_SMEM    (AT_QBYTES + 2*AT_STAGE) // 143360

__global__ __launch_bounds__(256, 1)
void attn_mma_kernel()
{
    extern __shared__ char smraw[];
    const uint32_t sbase = smem_u32(smraw);
    const int tid = threadIdx.x, wid = tid >> 5, lane = tid & 31;
    const int bh = blockIdx.y;
    const int q0 = blockIdx.x * 128;

    const char* Qbase = (const char*)(g_Qs + ((size_t)bh*TT + q0) * 128);
    const char* Kbase = (const char*)(g_Ks + (size_t)bh*TT*128);
    const char* Vh    = (const char*)(g_Vt + (size_t)bh*DH*TT);

    // Q tile -> smem
#pragma unroll
    for (int i = 0; i < 8; i++) {
        int u = tid + i*256;
        int row = u >> 4, cb = (u & 15) << 4;
        cp_async16(sbase + row*AT_QSTRIDE + cb, Qbase + (size_t)row*256 + cb);
    }
    CP_COMMIT();

    auto LOADC = [&](int c) {
        const uint32_t s = sbase + AT_QBYTES + (c & 1) * AT_STAGE;
        const char* ksrc = Kbase + (size_t)c*128*256;
        const char* vhs  = Vh + (size_t)c*256;
#pragma unroll
        for (int i = 0; i < 4; i++) {
            int u = tid + i*256;
            int r = u >> 3, kb = (u & 7) << 4;
            cp_async16(s           + r*144 + kb, ksrc + (size_t)r*256 + kb);
            cp_async16(s + AT_KARR + r*144 + kb, ksrc + (size_t)r*256 + 128 + kb);
        }
#pragma unroll
        for (int i = 0; i < 4; i++) {
            int u = tid + i*256;
            int r = u >> 4, kb = (u & 15) << 4;
            cp_async16(s + 2*AT_KARR + r*272 + kb, vhs + (size_t)r*4096 + kb);
        }
    };

    LOADC(0); CP_COMMIT();
    CP_WAIT1();
    __syncthreads();

    uint32_t qh[4][4], ql[4][4];
#pragma unroll
    for (int j = 0; j < 4; j++) {
        uint32_t base = sbase + (wid*16 + (lane & 15))*AT_QSTRIDE + j*32 + ((lane >> 4) << 4);
        ldsm4(qh[j][0], qh[j][1], qh[j][2], qh[j][3], base);
        ldsm4(ql[j][0], ql[j][1], ql[j][2], ql[j][3], base + 128);
    }

    float of[8][4];
#pragma unroll
    for (int f = 0; f < 8; f++)
#pragma unroll
        for (int c = 0; c < 4; c++) of[f][c] = 0.f;
    float m0 = -1e30f, m1 = -1e30f, l0 = 0.f, l1 = 0.f;

    for (int c = 0; c < 16; c++) {
        if (c + 1 < 16) LOADC(c + 1);
        CP_COMMIT();
        CP_WAIT1();
        __syncthreads();

        const uint32_t sK  = sbase + AT_QBYTES + (c & 1) * AT_STAGE;
        const uint32_t sKl = sK + AT_KARR;
        const uint32_t sVh = sK + 2*AT_KARR;

        float sfr[16][4];
#pragma unroll
        for (int f = 0; f < 16; f++)
#pragma unroll
            for (int r = 0; r < 4; r++) sfr[f][r] = 0.f;

#pragma unroll
        for (int j = 0; j < 4; j++) {
            const uint32_t cb = j*32 + ((lane >> 4) << 4);
#pragma unroll
            for (int nf2 = 0; nf2 < 8; nf2++) {     // K hi: qh + ql
                uint32_t r0, r1, r2, r3;
                ldsm4(r0, r1, r2, r3, sK + (nf2*16 + (lane & 15))*144 + cb);
                uint32_t b0[2] = {r0, r2}, b1[2] = {r1, r3};
                mma_bf16(sfr[2*nf2  ], qh[j], b0);
                mma_bf16(sfr[2*nf2  ], ql[j], b0);
                mma_bf16(sfr[2*nf2+1], qh[j], b1);
                mma_bf16(sfr[2*nf2+1], ql[j], b1);
            }
#pragma unroll
            for (int nf2 = 0; nf2 < 8; nf2++) {     // K lo: qh only
                uint32_t r0, r1, r2, r3;
                ldsm4(r0, r1, r2, r3, sKl + (nf2*16 + (lane & 15))*144 + cb);
                uint32_t b0[2] = {r0, r2}, b1[2] = {r1, r3};
                mma_bf16(sfr[2*nf2  ], qh[j], b0);
                mma_bf16(sfr[2*nf2+1], qh[j], b1);
            }
        }

        // online softmax (exp2 domain)
        float mx0 = sfr[0][0], mx1 = sfr[0][2];
#pragma unroll
        for (int f = 0; f < 16; f++) {
            mx0 = fmaxf(mx0, fmaxf(sfr[f][0], sfr[f][1]));
            mx1 = fmaxf(mx1, fmaxf(sfr[f][2], sfr[f][3]));
        }
        mx0 = fmaxf(mx0, __shfl_xor_sync(0xffffffffu, mx0, 1));
        mx0 = fmaxf(mx0, __shfl_xor_sync(0xffffffffu, mx0, 2));
        mx1 = fmaxf(mx1, __shfl_xor_sync(0xffffffffu, mx1, 1));
        mx1 = fmaxf(mx1, __shfl_xor_sync(0xffffffffu, mx1, 2));
        const float m0n = fmaxf(m0, mx0), m1n = fmaxf(m1, mx1);
        const float corr0 = ex2f(m0 - m0n), corr1 = ex2f(m1 - m1n);

        uint32_t pa[8][4];
        float l0a = 0.f, l1a = 0.f;
#pragma unroll
        for (int f = 0; f < 16; f++) {
            uint32_t p01 = ex2_h2(f2h2u(sfr[f][0] - m0n, sfr[f][1] - m0n));
            uint32_t p23 = ex2_h2(f2h2u(sfr[f][2] - m1n, sfr[f][3] - m1n));
            const int j = f >> 1;
            if (f & 1) { pa[j][2] = p01; pa[j][3] = p23; }
            else       { pa[j][0] = p01; pa[j][1] = p23; }
            float2 a = h2u2f2(p01); l0a += a.x + a.y;
            float2 bs = h2u2f2(p23); l1a += bs.x + bs.y;
        }
        l0a += __shfl_xor_sync(0xffffffffu, l0a, 1);
        l0a += __shfl_xor_sync(0xffffffffu, l0a, 2);
        l1a += __shfl_xor_sync(0xffffffffu, l1a, 1);
        l1a += __shfl_xor_sync(0xffffffffu, l1a, 2);
        l0 = l0 * corr0 + l0a;
        l1 = l1 * corr1 + l1a;
        m0 = m0n; m1 = m1n;

#pragma unroll
        for (int f = 0; f < 8; f++) {
            of[f][0] *= corr0; of[f][1] *= corr0;
            of[f][2] *= corr1; of[f][3] *= corr1;
        }

        // PV: single f16 V
#pragma unroll
        for (int j = 0; j < 8; j++) {
            const uint32_t cb = j*32 + ((lane >> 4) << 4);
#pragma unroll
            for (int nf2 = 0; nf2 < 4; nf2++) {
                uint32_t r0, r1, r2, r3;
                ldsm4(r0, r1, r2, r3, sVh + (nf2*16 + (lane & 15))*272 + cb);
                uint32_t b0[2] = {r0, r2}, b1[2] = {r1, r3};
                mma_f16(of[2*nf2  ], pa[j], b0);
                mma_f16(of[2*nf2+1], pa[j], b1);
            }
        }
        __syncthreads();
    }

    // epilogue -> g_O2 split [row][2048]
    const float inv0 = 1.f / l0, inv1 = 1.f / l1;
    const int b = bh >> 4, h = bh & 15;
    const int g = lane >> 2, t = lane & 3;
    const int qrow = q0 + wid*16 + g;
#pragma unroll
    for (int f = 0; f < 8; f++) {
        const int col = h*DH + f*8 + t*2;
#pragma unroll
        for (int rr = 0; rr < 2; rr++) {
            const size_t row = (size_t)(b*TT) + qrow + rr*8;
            const float inv = rr ? inv1 : inv0;
            uint32_t hi, lo;
            split2(of[f][rr*2] * inv, of[f][rr*2+1] * inv, hi, lo);
            *(uint32_t*)&g_O2[row*2048 + col]        = hi;
            *(uint32_t*)&g_O2[row*2048 + 1024 + col] = lo;
        }
    }
}

// ---------------------------------------------------------------------------
// Launch. Inputs: 0=x, 1=mask, 2=Wq, 3=Wk, 4=Wv, 5=Wo, 6=S_q, 7=S_k
// Order: weff_all, cvt_x, qkv_gemm, attn (<- ncu capture slot), out_gemm.
// ---------------------------------------------------------------------------
extern "C" void kernel_launch(void* const* d_in, const int* in_sizes, int n_in,
                              void* d_out, int out_size)
{
    const float* x  = (const float*)d_in[0];
    const float* Wq = (const float*)d_in[2];
    const float* Wk = (const float*)d_in[3];
    const float* Wv = (const float*)d_in[4];
    const float* Wo = (const float*)d_in[5];
    const float* Sq = (const float*)d_in[6];
    const float* Sk = (const float*)d_in[7];
    float* outp = (float*)d_out;

    __nv_bfloat16 *dA2, *dO2, *dWQ2, *dWK2, *dWV2, *dWO2;
    cudaGetSymbolAddress((void**)&dA2,  g_A2);
    cudaGetSymbolAddress((void**)&dO2,  g_O2);
    cudaGetSymbolAddress((void**)&dWQ2, g_WQ2);
    cudaGetSymbolAddress((void**)&dWK2, g_WK2);
    cudaGetSymbolAddress((void**)&dWV2, g_WV2);
    cudaGetSymbolAddress((void**)&dWO2, g_WO2);

    cudaFuncSetAttribute(gemm_mma2_kernel<0>, cudaFuncAttributeMaxDynamicSharedMemorySize, G2_SMEM);
    cudaFuncSetAttribute(gemm_mma2_kernel<1>, cudaFuncAttributeMaxDynamicSharedMemorySize, G2_SMEM);
    cudaFuncSetAttribute(attn_mma_kernel, cudaFuncAttributeMaxDynamicSharedMemorySize, AT_SMEM);

    // 1) weight prep: fold+split Wq/Wk, split Wv/Wo
    weff_all_kernel<<<dim3(DD/256, HH, 4), 256>>>(Wq, Wk, Wv, Wo, Sq, Sk);

    // 2) split x
    cvt_split_kernel<<<(MM*DD)/256, 256>>>(x, dA2, MM*DD);

    // 3) merged QKV projection (HMMA) -> g_Qs, g_Ks, g_Vt
    const float qscale = 0.125f * 1.4426950408889634f;   // scale * log2(e)
    gemm_mma2_kernel<1><<<dim3(24, MM/128), 256, G2_SMEM>>>(dA2, dWQ2, dWK2, dWV2, nullptr, qscale);

    // 4) flash attention (HMMA) -> g_O2   [ncu capture slot]
    attn_mma_kernel<<<dim3(TT/128, BH), 256, AT_SMEM>>>();

    // 5) output projection (HMMA) -> d_out fp32
    gemm_mma2_kernel<0><<<dim3(8, MM/128), 256, G2_SMEM>>>(dO2, dWO2, dWO2, dWO2, outp, 1.0f);
}

// round 10
// speedup vs baseline: 4.8402x; 1.0159x over previous
#include <cuda_runtime.h>
#include <cuda_bf16.h>
#include <cuda_fp16.h>
#include <math.h>
#include <stdint.h>

// Shapes (fixed)
#define BB 2
#define TT 2048
#define DD 1024
#define HH 16
#define DH 64
#define MM (BB*TT)   // 4096
#define BH (BB*HH)   // 32

// ---------------------------------------------------------------------------
// Scratch (no cudaMalloc allowed)
// ---------------------------------------------------------------------------
__device__ __nv_bfloat16 g_A2 [MM*2*DD];      // x split [rows][hi1024|lo1024]
__device__ __nv_bfloat16 g_O2 [MM*2*DD];      // attention output split
__device__ __nv_bfloat16 g_WQ2[DD*2*DD];      // folded Wq split
__device__ __nv_bfloat16 g_WK2[DD*2*DD];      // folded Wk split
__device__ __nv_bfloat16 g_WV2[DD*2*DD];
__device__ __nv_bfloat16 g_WO2[DD*2*DD];
__device__ __nv_bfloat16 g_Qs[BH*TT*128];     // [bh][t][hi64|lo64], Q pre-scaled
__device__ __nv_bfloat16 g_Ks[BH*TT*128];     // [bh][t][hi64|lo64]
__device__ __half        g_Vt[BH*DH*TT];      // [bh][d][s]  (f16, transposed)

// ---------------------------------------------------------------------------
// PTX helpers (sm_80-level only — ptxas targets plain sm_103, no tcgen05/TMA)
// ---------------------------------------------------------------------------
__device__ __forceinline__ uint32_t smem_u32(const void* p) {
    uint32_t a;
    asm("{ .reg .u64 t; cvta.to.shared.u64 t, %1; cvt.u32.u64 %0, t; }" : "=r"(a) : "l"(p));
    return a;
}
__device__ __forceinline__ void cp_async16(uint32_t dst, const void* src) {
    asm volatile("cp.async.cg.shared.global [%0], [%1], 16;\n" :: "r"(dst), "l"(src));
}
#define CP_COMMIT() asm volatile("cp.async.commit_group;\n" ::: "memory")
#define CP_WAIT1()  asm volatile("cp.async.wait_group 1;\n" ::: "memory")

__device__ __forceinline__ void ldsm4(uint32_t &r0, uint32_t &r1, uint32_t &r2, uint32_t &r3,
                                      uint32_t addr) {
    asm volatile("ldmatrix.sync.aligned.m8n8.x4.shared.b16 {%0,%1,%2,%3}, [%4];"
                 : "=r"(r0), "=r"(r1), "=r"(r2), "=r"(r3) : "r"(addr));
}
__device__ __forceinline__ void mma_bf16(float* c, const uint32_t* a, const uint32_t* b) {
    asm volatile("mma.sync.aligned.m16n8k16.row.col.f32.bf16.bf16.f32 "
                 "{%0,%1,%2,%3}, {%4,%5,%6,%7}, {%8,%9}, {%0,%1,%2,%3};"
                 : "+f"(c[0]), "+f"(c[1]), "+f"(c[2]), "+f"(c[3])
                 : "r"(a[0]), "r"(a[1]), "r"(a[2]), "r"(a[3]), "r"(b[0]), "r"(b[1]));
}
__device__ __forceinline__ void mma_f16(float* c, const uint32_t* a, const uint32_t* b) {
    asm volatile("mma.sync.aligned.m16n8k16.row.col.f32.f16.f16.f32 "
                 "{%0,%1,%2,%3}, {%4,%5,%6,%7}, {%8,%9}, {%0,%1,%2,%3};"
                 : "+f"(c[0]), "+f"(c[1]), "+f"(c[2]), "+f"(c[3])
                 : "r"(a[0]), "r"(a[1]), "r"(a[2]), "r"(a[3]), "r"(b[0]), "r"(b[1]));
}
__device__ __forceinline__ float ex2f(float x) {
    float r; asm("ex2.approx.ftz.f32 %0, %1;" : "=f"(r) : "f"(x)); return r;
}
__device__ __forceinline__ uint32_t ex2_h2(uint32_t x) {
    uint32_t r; asm("ex2.approx.f16x2 %0, %1;" : "=r"(r) : "r"(x)); return r;
}
__device__ __forceinline__ uint32_t f2h2u(float a, float b) {
    __half2 h = __floats2half2_rn(a, b);
    return *reinterpret_cast<uint32_t*>(&h);
}
__device__ __forceinline__ float2 h2u2f2(uint32_t u) {
    __half2 h = *reinterpret_cast<__half2*>(&u);
    return __half22float2(h);
}
__device__ __forceinline__ uint32_t pack_bf16(float a, float b) {
    __nv_bfloat162 h = __floats2bfloat162_rn(a, b);
    return *reinterpret_cast<uint32_t*>(&h);
}
__device__ __forceinline__ void split2(float v0, float v1, uint32_t &hi, uint32_t &lo) {
    __nv_bfloat16 h0 = __float2bfloat16(v0);
    __nv_bfloat16 h1 = __float2bfloat16(v1);
    float l0 = v0 - __bfloat162float(h0);
    float l1 = v1 - __bfloat162float(h1);
    uint32_t u0 = (uint32_t)*reinterpret_cast<uint16_t*>(&h0);
    uint32_t u1 = (uint32_t)*reinterpret_cast<uint16_t*>(&h1);
    hi = u0 | (u1 << 16);
    lo = pack_bf16(l0, l1);
}

// ---------------------------------------------------------------------------
// weff_all: z=0/1 fold+split Wq/Wk with S; z=2/3 plain split of Wv/Wo.
// ---------------------------------------------------------------------------
__global__ __launch_bounds__(256)
void weff_all_kernel(const float* __restrict__ Wq, const float* __restrict__ Wk,
                     const float* __restrict__ Wv, const float* __restrict__ Wo,
                     const float* __restrict__ Sq, const float* __restrict__ Sk)
{
    const int h = blockIdx.y;
    const int z = blockIdx.z;
    const int d = blockIdx.x * 256 + threadIdx.x;

    if (z < 2) {
        const float* __restrict__ W = z ? Wk : Wq;
        const float* __restrict__ S = z ? Sk : Sq;
        __nv_bfloat16* __restrict__ outp = z ? g_WK2 : g_WQ2;

        __shared__ float s_s[DH*DH];
        for (int i = threadIdx.x; i < DH*DH; i += 256) s_s[i] = S[h*DH*DH + i];
        __syncthreads();

        float acc[DH];
#pragma unroll
        for (int e = 0; e < DH; e++) acc[e] = 0.f;
        for (int c = 0; c < DH; c++) {
            const float w = W[(h*DH + c)*DD + d];
#pragma unroll
            for (int e = 0; e < DH; e++) acc[e] += w * s_s[c*DH + e];
        }
#pragma unroll
        for (int e = 0; e < DH; e++) {
            float v = acc[e];
            __nv_bfloat16 hi = __float2bfloat16(v);
            float lo = v - __bfloat162float(hi);
            outp[(size_t)(h*DH + e)*2048 + d] = hi;
            outp[(size_t)(h*DH + e)*2048 + 1024 + d] = __float2bfloat16(lo);
        }
    } else {
        const float* __restrict__ W = (z == 2) ? Wv : Wo;
        __nv_bfloat16* __restrict__ outp = (z == 2) ? g_WV2 : g_WO2;
        for (int c = 0; c < DH; c++) {
            const int row = h*DH + c;
            float v = W[(size_t)row*DD + d];
            __nv_bfloat16 hi = __float2bfloat16(v);
            float lo = v - __bfloat162float(hi);
            outp[(size_t)row*2048 + d] = hi;
            outp[(size_t)row*2048 + 1024 + d] = __float2bfloat16(lo);
        }
    }
}

// ---------------------------------------------------------------------------
// fp32 -> bf16 hi/lo split (x only)
// ---------------------------------------------------------------------------
__global__ __launch_bounds__(256)
void cvt_split_kernel(const float* __restrict__ src, __nv_bfloat16* __restrict__ dst, int n)
{
    int i = blockIdx.x * 256 + threadIdx.x;
    if (i >= n) return;
    int r = i >> 10, c = i & 1023;
    float v = src[i];
    __nv_bfloat16 hi = __float2bfloat16(v);
    float lof = v - __bfloat162float(hi);
    dst[(size_t)r*2048 + c] = hi;
    dst[(size_t)r*2048 + 1024 + c] = __float2bfloat16(lof);
}

// ---------------------------------------------------------------------------
// Merged QKV GEMM (QKV=1): grid (24, 32). superblock 0-7->Q, 8-15->K, 16-23->V.
// V epilogue transposes through smem for coalesced f16 [bh][d][s] stores.
// QKV=0: plain fp32 C (output projection), grid (8, 32).
// ---------------------------------------------------------------------------
#define G2_TILE  (128*144)
#define G2_STAGE (4*G2_TILE)
#define G2_SMEM  (2*G2_STAGE)

template<int QKV>
__global__ __launch_bounds__(256, 1)
void gemm_mma2_kernel(const __nv_bfloat16* __restrict__ A2,
                      const __nv_bfloat16* __restrict__ Bq,
                      const __nv_bfloat16* __restrict__ Bk,
                      const __nv_bfloat16* __restrict__ Bv,
                      float* __restrict__ C, float qscale)
{
    extern __shared__ char smraw[];
    const uint32_t sbase = smem_u32(smraw);
    const int tid = threadIdx.x;
    const int wid = tid >> 5, lane = tid & 31;
    const int warp_m = wid >> 1, warp_n = wid & 1;
    const int m0 = blockIdx.y * 128;
    const int nb = QKV ? (blockIdx.x >> 3) : 0;         // 0=Q,1=K,2=V
    const int n0 = QKV ? ((blockIdx.x & 7) * 128) : (blockIdx.x * 128);
    const __nv_bfloat16* __restrict__ B2 =
        QKV ? ((nb == 0) ? Bq : (nb == 1) ? Bk : Bv) : Bq;

    float acc[2][8][4];
#pragma unroll
    for (int a = 0; a < 2; a++)
#pragma unroll
        for (int b = 0; b < 8; b++)
#pragma unroll
            for (int c = 0; c < 4; c++) acc[a][b][c] = 0.f;

    auto LOAD = [&](int it) {
        const uint32_t st = sbase + (it & 1) * G2_STAGE;
        const char* gAh = (const char*)(A2 + (size_t)m0*2048 + it*64);
        const char* gBh = (const char*)(B2 + (size_t)n0*2048 + it*64);
#pragma unroll
        for (int i = 0; i < 4; i++) {
            int u = tid + i*256;
            int row = u >> 3, kb = (u & 7) << 4;
            const size_t go = (size_t)row*4096 + kb;
            const uint32_t so = row*144 + kb;
            cp_async16(st             + so, gAh + go);
            cp_async16(st +   G2_TILE + so, gAh + 2048 + go);
            cp_async16(st + 2*G2_TILE + so, gBh + go);
            cp_async16(st + 3*G2_TILE + so, gBh + 2048 + go);
        }
    };

    LOAD(0); CP_COMMIT();
    LOAD(1); CP_COMMIT();

    const int NIT = 16;
    for (int it = 0; it < NIT; it++) {
        CP_WAIT1();
        __syncthreads();
        const uint32_t st = sbase + (it & 1) * G2_STAGE;
#pragma unroll
        for (int j = 0; j < 4; j++) {
            const uint32_t cb = j*32 + ((lane >> 4) << 4);
            uint32_t ah[2][4], al[2][4];
#pragma unroll
            for (int mf = 0; mf < 2; mf++) {
                const uint32_t ro = (warp_m*32 + mf*16 + (lane & 15))*144 + cb;
                ldsm4(ah[mf][0], ah[mf][1], ah[mf][2], ah[mf][3], st + ro);
                ldsm4(al[mf][0], al[mf][1], al[mf][2], al[mf][3], st + G2_TILE + ro);
            }
            uint32_t bh[8][2], bl[8][2];
#pragma unroll
            for (int nf2 = 0; nf2 < 4; nf2++) {
                const uint32_t ro = (warp_n*64 + nf2*16 + (lane & 15))*144 + cb;
                uint32_t r0, r1, r2, r3;
                ldsm4(r0, r1, r2, r3, st + 2*G2_TILE + ro);
                bh[nf2*2][0] = r0; bh[nf2*2][1] = r2;
                bh[nf2*2+1][0] = r1; bh[nf2*2+1][1] = r3;
                ldsm4(r0, r1, r2, r3, st + 3*G2_TILE + ro);
                bl[nf2*2][0] = r0; bl[nf2*2][1] = r2;
                bl[nf2*2+1][0] = r1; bl[nf2*2+1][1] = r3;
            }
#pragma unroll
            for (int mf = 0; mf < 2; mf++)
#pragma unroll
                for (int nf = 0; nf < 8; nf++) {
                    mma_bf16(acc[mf][nf], ah[mf], bh[nf]);
                    mma_bf16(acc[mf][nf], ah[mf], bl[nf]);
                    mma_bf16(acc[mf][nf], al[mf], bh[nf]);
                }
        }
        __syncthreads();
        if (it + 2 < NIT) LOAD(it + 2);
        CP_COMMIT();
    }

    const int g = lane >> 2, t = lane & 3;
    if (!QKV || nb < 2) {
#pragma unroll
        for (int mf = 0; mf < 2; mf++) {
            const int row0 = m0 + warp_m*32 + mf*16 + g;
#pragma unroll
            for (int nf = 0; nf < 8; nf++) {
                const int col = n0 + warp_n*64 + nf*8 + t*2;
                if (!QKV) {
                    *(float2*)&C[(size_t)row0*DD + col]     = make_float2(acc[mf][nf][0], acc[mf][nf][1]);
                    *(float2*)&C[(size_t)(row0+8)*DD + col] = make_float2(acc[mf][nf][2], acc[mf][nf][3]);
                } else {
                    __nv_bfloat16* dst = (nb == 0) ? g_Qs : g_Ks;
                    const float sc = (nb == 0) ? qscale : 1.0f;
                    const int h = col >> 6, e = col & 63;
#pragma unroll
                    for (int rr = 0; rr < 2; rr++) {
                        const int row = row0 + rr*8;
                        const int b = row >> 11, tq = row & 2047;
                        const size_t base = ((size_t)(b*HH + h)*TT + tq) << 7;
                        uint32_t hi, lo;
                        split2(acc[mf][nf][rr*2] * sc, acc[mf][nf][rr*2+1] * sc, hi, lo);
                        *(uint32_t*)&dst[base + e]      = hi;
                        *(uint32_t*)&dst[base + 64 + e] = lo;
                    }
                }
            }
        }
    } else {
        // V: transpose through smem -> coalesced f16 stores to g_Vt [bh][d][s]
        __half* sm = (__half*)smraw;            // tile [tq 128][d 128], stride 136 halves
        __syncthreads();
#pragma unroll
        for (int mf = 0; mf < 2; mf++) {
            const int rowl = warp_m*32 + mf*16 + g;
#pragma unroll
            for (int nf = 0; nf < 8; nf++) {
                const int col = warp_n*64 + nf*8 + t*2;
#pragma unroll
                for (int rr = 0; rr < 2; rr++) {
                    __half2 hv = __floats2half2_rn(acc[mf][nf][rr*2], acc[mf][nf][rr*2+1]);
                    *(__half2*)(sm + (size_t)(rowl + rr*8)*136 + col) = hv;
                }
            }
        }
        __syncthreads();
        const int dd = tid >> 1, th = tid & 1;
        const int h = (n0 + dd) >> 6, dl = (n0 + dd) & 63;
        const int b = m0 >> 11;
        const int tq0 = (m0 & 2047) + th*64;
        __half* dst = g_Vt + ((size_t)((b*HH + h)*DH + dl))*TT + tq0;
#pragma unroll
        for (int i8 = 0; i8 < 8; i8++) {
            __half tmp[8];
#pragma unroll
            for (int k = 0; k < 8; k++)
                tmp[k] = sm[(size_t)(th*64 + i8*8 + k)*136 + dd];
            *(uint4*)(dst + i8*8) = *(uint4*)tmp;
        }
    }
}

// ---------------------------------------------------------------------------
// Flash attention on HMMA — 512 threads (16 warps, 4/SMSP), 256-query CTA,
// 64-key chunks, 3-stage pipeline, one __syncthreads per chunk.
// Per-lane deferred l-reduction; ql reloaded per chunk (reg budget <= 128).
// ---------------------------------------------------------------------------
#define AT_QSTRIDE 272
#define AT_QBYTES  (256*272)                 // 69632
#define AT_KARR    (64*144)                  // 9216 (Khi / Klo / V each)
#define AT_NST     3
#define AT_STAGE   (3*AT_KARR)               // 27648
#define AT_SMEM    (AT_QBYTES + AT_NST*AT_STAGE)   // 152576

__global__ __launch_bounds__(512, 1)
void attn_mma_kernel()
{
    extern __shared__ char smraw[];
    const uint32_t sbase = smem_u32(smraw);
    const int tid = threadIdx.x, wid = tid >> 5, lane = tid & 31;
    const int bh = blockIdx.y;
    const int q0 = blockIdx.x * 256;

    const char* Qbase = (const char*)(g_Qs + ((size_t)bh*TT + q0) * 128);
    const char* Kbase = (const char*)(g_Ks + (size_t)bh*TT*128);
    const char* Vbase = (const char*)(g_Vt + (size_t)bh*DH*TT);

    // Q: 256 rows x 256B
#pragma unroll
    for (int i = 0; i < 8; i++) {
        int u = tid + i*512;
        int row = u >> 4, cb = (u & 15) << 4;
        cp_async16(sbase + row*AT_QSTRIDE + cb, Qbase + (size_t)row*256 + cb);
    }
    CP_COMMIT();

    auto LOADC = [&](int c) {
        const uint32_t s = sbase + AT_QBYTES + (c % AT_NST) * AT_STAGE;
        const char* ksrc = Kbase + (size_t)c*64*256;
        const char* vsrc = Vbase + (size_t)c*128;
        const int r = tid >> 3, kb = (tid & 7) << 4;
        cp_async16(s             + r*144 + kb, ksrc + (size_t)r*256 + kb);        // Khi
        cp_async16(s +   AT_KARR + r*144 + kb, ksrc + (size_t)r*256 + 128 + kb);  // Klo
        cp_async16(s + 2*AT_KARR + r*144 + kb, vsrc + (size_t)r*4096 + kb);       // V [d][s]
    };

    LOADC(0); CP_COMMIT();
    LOADC(1); CP_COMMIT();

    CP_WAIT1();               // Q + chunk 0 resident
    __syncthreads();

    // Q hi fragments resident; Q lo reloaded per chunk
    const uint32_t qfb = sbase + (wid*16 + (lane & 15))*AT_QSTRIDE + ((lane >> 4) << 4);
    uint32_t qh[4][4];
#pragma unroll
    for (int j = 0; j < 4; j++)
        ldsm4(qh[j][0], qh[j][1], qh[j][2], qh[j][3], qfb + j*32);

    float of[8][4];
#pragma unroll
    for (int f = 0; f < 8; f++)
#pragma unroll
        for (int c4 = 0; c4 < 4; c4++) of[f][c4] = 0.f;
    float m0 = -1e30f, m1 = -1e30f, l0 = 0.f, l1 = 0.f;

    for (int c = 0; c < 32; c++) {
        if (c > 0) { CP_WAIT1(); __syncthreads(); }
        if (c + 2 < 32) LOADC(c + 2);
        CP_COMMIT();

        const uint32_t sK = sbase + AT_QBYTES + (c % AT_NST) * AT_STAGE;

        // ---- scores (64 keys -> 8 n-fragments) ----
        float sfr[8][4];
#pragma unroll
        for (int f = 0; f < 8; f++)
#pragma unroll
            for (int r4 = 0; r4 < 4; r4++) sfr[f][r4] = 0.f;

#pragma unroll
        for (int j = 0; j < 4; j++) {
            const uint32_t cb = j*32 + ((lane >> 4) << 4);
            uint32_t ql[4];
            ldsm4(ql[0], ql[1], ql[2], ql[3], qfb + j*32 + 128);
#pragma unroll
            for (int nf2 = 0; nf2 < 4; nf2++) {       // K hi: qh + ql
                uint32_t r0, r1, r2, r3;
                ldsm4(r0, r1, r2, r3, sK + (nf2*16 + (lane & 15))*144 + cb);
                uint32_t b0[2] = {r0, r2}, b1[2] = {r1, r3};
                mma_bf16(sfr[2*nf2  ], qh[j], b0);
                mma_bf16(sfr[2*nf2  ], ql,    b0);
                mma_bf16(sfr[2*nf2+1], qh[j], b1);
                mma_bf16(sfr[2*nf2+1], ql,    b1);
            }
#pragma unroll
            for (int nf2 = 0; nf2 < 4; nf2++) {       // K lo: qh only
                uint32_t r0, r1, r2, r3;
                ldsm4(r0, r1, r2, r3, sK + AT_KARR + (nf2*16 + (lane & 15))*144 + cb);
                uint32_t b0[2] = {r0, r2}, b1[2] = {r1, r3};
                mma_bf16(sfr[2*nf2  ], qh[j], b0);
                mma_bf16(sfr[2*nf2+1], qh[j], b1);
            }
        }

        // ---- online softmax (exp2 domain) ----
        float mx0 = sfr[0][0], mx1 = sfr[0][2];
#pragma unroll
        for (int f = 0; f < 8; f++) {
            mx0 = fmaxf(mx0, fmaxf(sfr[f][0], sfr[f][1]));
            mx1 = fmaxf(mx1, fmaxf(sfr[f][2], sfr[f][3]));
        }
        mx0 = fmaxf(mx0, __shfl_xor_sync(0xffffffffu, mx0, 1));
        mx0 = fmaxf(mx0, __shfl_xor_sync(0xffffffffu, mx0, 2));
        mx1 = fmaxf(mx1, __shfl_xor_sync(0xffffffffu, mx1, 1));
        mx1 = fmaxf(mx1, __shfl_xor_sync(0xffffffffu, mx1, 2));
        const float m0n = fmaxf(m0, mx0), m1n = fmaxf(m1, mx1);
        const float corr0 = ex2f(m0 - m0n), corr1 = ex2f(m1 - m1n);

        uint32_t pa[4][4];
        float l0a = 0.f, l1a = 0.f;
#pragma unroll
        for (int f = 0; f < 8; f++) {
            uint32_t p01 = ex2_h2(f2h2u(sfr[f][0] - m0n, sfr[f][1] - m0n));
            uint32_t p23 = ex2_h2(f2h2u(sfr[f][2] - m1n, sfr[f][3] - m1n));
            const int j = f >> 1;
            if (f & 1) { pa[j][2] = p01; pa[j][3] = p23; }
            else       { pa[j][0] = p01; pa[j][1] = p23; }
            float2 a = h2u2f2(p01); l0a += a.x + a.y;
            float2 bs = h2u2f2(p23); l1a += bs.x + bs.y;
        }
        // deferred lane reduction: keep per-lane partials
        l0 = l0 * corr0 + l0a;
        l1 = l1 * corr1 + l1a;
        m0 = m0n; m1 = m1n;

#pragma unroll
        for (int f = 0; f < 8; f++) {
            of[f][0] *= corr0; of[f][1] *= corr0;
            of[f][2] *= corr1; of[f][3] *= corr1;
        }

        // ---- PV: single f16 V, 4 k-fragments ----
#pragma unroll
        for (int j = 0; j < 4; j++) {
            const uint32_t cb = j*32 + ((lane >> 4) << 4);
#pragma unroll
            for (int nf2 = 0; nf2 < 4; nf2++) {
                uint32_t r0, r1, r2, r3;
                ldsm4(r0, r1, r2, r3, sK + 2*AT_KARR + (nf2*16 + (lane & 15))*144 + cb);
                uint32_t b0[2] = {r0, r2}, b1[2] = {r1, r3};
                mma_f16(of[2*nf2  ], pa[j], b0);
                mma_f16(of[2*nf2+1], pa[j], b1);
            }
        }
    }

    // epilogue: lane-reduce l, normalize, write split O to g_O2
    l0 += __shfl_xor_sync(0xffffffffu, l0, 1);
    l0 += __shfl_xor_sync(0xffffffffu, l0, 2);
    l1 += __shfl_xor_sync(0xffffffffu, l1, 1);
    l1 += __shfl_xor_sync(0xffffffffu, l1, 2);
    const float inv0 = 1.f / l0, inv1 = 1.f / l1;
    const int b = bh >> 4, h = bh & 15;
    const int g = lane >> 2, t = lane & 3;
    const int qrow = q0 + wid*16 + g;
#pragma unroll
    for (int f = 0; f < 8; f++) {
        const int col = h*DH + f*8 + t*2;
#pragma unroll
        for (int rr = 0; rr < 2; rr++) {
            const size_t row = (size_t)(b*TT) + qrow + rr*8;
            const float inv = rr ? inv1 : inv0;
            uint32_t hi, lo;
            split2(of[f][rr*2] * inv, of[f][rr*2+1] * inv, hi, lo);
            *(uint32_t*)&g_O2[row*2048 + col]        = hi;
            *(uint32_t*)&g_O2[row*2048 + 1024 + col] = lo;
        }
    }
}

// ---------------------------------------------------------------------------
// Launch. Inputs: 0=x, 1=mask, 2=Wq, 3=Wk, 4=Wv, 5=Wo, 6=S_q, 7=S_k
// Order: weff_all, cvt_x, qkv_gemm, attn (ncu slot), out_gemm.
// ---------------------------------------------------------------------------
extern "C" void kernel_launch(void* const* d_in, const int* in_sizes, int n_in,
                              void* d_out, int out_size)
{
    const float* x  = (const float*)d_in[0];
    const float* Wq = (const float*)d_in[2];
    const float* Wk = (const float*)d_in[3];
    const float* Wv = (const float*)d_in[4];
    const float* Wo = (const float*)d_in[5];
    const float* Sq = (const float*)d_in[6];
    const float* Sk = (const float*)d_in[7];
    float* outp = (float*)d_out;

    __nv_bfloat16 *dA2, *dO2, *dWQ2, *dWK2, *dWV2, *dWO2;
    cudaGetSymbolAddress((void**)&dA2,  g_A2);
    cudaGetSymbolAddress((void**)&dO2,  g_O2);
    cudaGetSymbolAddress((void**)&dWQ2, g_WQ2);
    cudaGetSymbolAddress((void**)&dWK2, g_WK2);
    cudaGetSymbolAddress((void**)&dWV2, g_WV2);
    cudaGetSymbolAddress((void**)&dWO2, g_WO2);

    cudaFuncSetAttribute(gemm_mma2_kernel<0>, cudaFuncAttributeMaxDynamicSharedMemorySize, G2_SMEM);
    cudaFuncSetAttribute(gemm_mma2_kernel<1>, cudaFuncAttributeMaxDynamicSharedMemorySize, G2_SMEM);
    cudaFuncSetAttribute(attn_mma_kernel, cudaFuncAttributeMaxDynamicSharedMemorySize, AT_SMEM);

    // 1) weight prep
    weff_all_kernel<<<dim3(DD/256, HH, 4), 256>>>(Wq, Wk, Wv, Wo, Sq, Sk);

    // 2) split x
    cvt_split_kernel<<<(MM*DD)/256, 256>>>(x, dA2, MM*DD);

    // 3) merged QKV projection -> g_Qs, g_Ks, g_Vt
    const float qscale = 0.125f * 1.4426950408889634f;   // scale * log2(e)
    gemm_mma2_kernel<1><<<dim3(24, MM/128), 256, G2_SMEM>>>(dA2, dWQ2, dWK2, dWV2, nullptr, qscale);

    // 4) flash attention -> g_O2   [ncu capture slot]
    attn_mma_kernel<<<dim3(TT/256, BH), 512, AT_SMEM>>>();

    // 5) output projection -> d_out fp32
    gemm_mma2_kernel<0><<<dim3(8, MM/128), 256, G2_SMEM>>>(dO2, dWO2, dWO2, dWO2, outp, 1.0f);
}

// round 11
// speedup vs baseline: 4.9981x; 1.0326x over previous
#include <cuda_runtime.h>
#include <cuda_bf16.h>
#include <cuda_fp16.h>
#include <math.h>
#include <stdint.h>

// Shapes (fixed)
#define BB 2
#define TT 2048
#define DD 1024
#define HH 16
#define DH 64
#define MM (BB*TT)   // 4096
#define BH (BB*HH)   // 32

// ---------------------------------------------------------------------------
// Scratch (no cudaMalloc allowed)
// ---------------------------------------------------------------------------
__device__ __nv_bfloat16 g_A2 [MM*2*DD];      // x split [rows][hi1024|lo1024]
__device__ __nv_bfloat16 g_O2 [MM*2*DD];      // attention output split
__device__ __nv_bfloat16 g_WQ2[DD*2*DD];      // folded Wq split
__device__ __nv_bfloat16 g_WK2[DD*2*DD];      // folded Wk split
__device__ __nv_bfloat16 g_WV2[DD*2*DD];
__device__ __nv_bfloat16 g_WO2[DD*2*DD];
__device__ __nv_bfloat16 g_Qs[BH*TT*128];     // [bh][t][hi64|lo64], Q pre-scaled
__device__ __nv_bfloat16 g_Ks[BH*TT*128];     // [bh][t][hi64|lo64]
__device__ __half        g_Vt[BH*DH*TT];      // [bh][d][s]  (f16, transposed)

// ---------------------------------------------------------------------------
// PTX helpers (sm_80-level only — ptxas targets plain sm_103, no tcgen05/TMA)
// ---------------------------------------------------------------------------
__device__ __forceinline__ uint32_t smem_u32(const void* p) {
    uint32_t a;
    asm("{ .reg .u64 t; cvta.to.shared.u64 t, %1; cvt.u32.u64 %0, t; }" : "=r"(a) : "l"(p));
    return a;
}
__device__ __forceinline__ void cp_async16(uint32_t dst, const void* src) {
    asm volatile("cp.async.cg.shared.global [%0], [%1], 16;\n" :: "r"(dst), "l"(src));
}
#define CP_COMMIT() asm volatile("cp.async.commit_group;\n" ::: "memory")
#define CP_WAIT1()  asm volatile("cp.async.wait_group 1;\n" ::: "memory")

__device__ __forceinline__ void ldsm4(uint32_t &r0, uint32_t &r1, uint32_t &r2, uint32_t &r3,
                                      uint32_t addr) {
    asm volatile("ldmatrix.sync.aligned.m8n8.x4.shared.b16 {%0,%1,%2,%3}, [%4];"
                 : "=r"(r0), "=r"(r1), "=r"(r2), "=r"(r3) : "r"(addr));
}
__device__ __forceinline__ void mma_bf16(float* c, const uint32_t* a, const uint32_t* b) {
    asm volatile("mma.sync.aligned.m16n8k16.row.col.f32.bf16.bf16.f32 "
                 "{%0,%1,%2,%3}, {%4,%5,%6,%7}, {%8,%9}, {%0,%1,%2,%3};"
                 : "+f"(c[0]), "+f"(c[1]), "+f"(c[2]), "+f"(c[3])
                 : "r"(a[0]), "r"(a[1]), "r"(a[2]), "r"(a[3]), "r"(b[0]), "r"(b[1]));
}
__device__ __forceinline__ void mma_f16(float* c, const uint32_t* a, const uint32_t* b) {
    asm volatile("mma.sync.aligned.m16n8k16.row.col.f32.f16.f16.f32 "
                 "{%0,%1,%2,%3}, {%4,%5,%6,%7}, {%8,%9}, {%0,%1,%2,%3};"
                 : "+f"(c[0]), "+f"(c[1]), "+f"(c[2]), "+f"(c[3])
                 : "r"(a[0]), "r"(a[1]), "r"(a[2]), "r"(a[3]), "r"(b[0]), "r"(b[1]));
}
__device__ __forceinline__ float ex2f(float x) {
    float r; asm("ex2.approx.ftz.f32 %0, %1;" : "=f"(r) : "f"(x)); return r;
}
__device__ __forceinline__ uint32_t ex2_h2(uint32_t x) {
    uint32_t r; asm("ex2.approx.f16x2 %0, %1;" : "=r"(r) : "r"(x)); return r;
}
__device__ __forceinline__ uint32_t f2h2u(float a, float b) {
    __half2 h = __floats2half2_rn(a, b);
    return *reinterpret_cast<uint32_t*>(&h);
}
__device__ __forceinline__ float2 h2u2f2(uint32_t u) {
    __half2 h = *reinterpret_cast<__half2*>(&u);
    return __half22float2(h);
}
__device__ __forceinline__ uint32_t pack_bf16(float a, float b) {
    __nv_bfloat162 h = __floats2bfloat162_rn(a, b);
    return *reinterpret_cast<uint32_t*>(&h);
}
__device__ __forceinline__ void split2(float v0, float v1, uint32_t &hi, uint32_t &lo) {
    __nv_bfloat16 h0 = __float2bfloat16(v0);
    __nv_bfloat16 h1 = __float2bfloat16(v1);
    float l0 = v0 - __bfloat162float(h0);
    float l1 = v1 - __bfloat162float(h1);
    uint32_t u0 = (uint32_t)*reinterpret_cast<uint16_t*>(&h0);
    uint32_t u1 = (uint32_t)*reinterpret_cast<uint16_t*>(&h1);
    hi = u0 | (u1 << 16);
    lo = pack_bf16(l0, l1);
}

// ---------------------------------------------------------------------------
// weff_all: z=0/1 fold+split Wq/Wk with S; z=2/3 plain split of Wv/Wo.
// ---------------------------------------------------------------------------
__global__ __launch_bounds__(256)
void weff_all_kernel(const float* __restrict__ Wq, const float* __restrict__ Wk,
                     const float* __restrict__ Wv, const float* __restrict__ Wo,
                     const float* __restrict__ Sq, const float* __restrict__ Sk)
{
    const int h = blockIdx.y;
    const int z = blockIdx.z;
    const int d = blockIdx.x * 256 + threadIdx.x;

    if (z < 2) {
        const float* __restrict__ W = z ? Wk : Wq;
        const float* __restrict__ S = z ? Sk : Sq;
        __nv_bfloat16* __restrict__ outp = z ? g_WK2 : g_WQ2;

        __shared__ float s_s[DH*DH];
        for (int i = threadIdx.x; i < DH*DH; i += 256) s_s[i] = S[h*DH*DH + i];
        __syncthreads();

        float acc[DH];
#pragma unroll
        for (int e = 0; e < DH; e++) acc[e] = 0.f;
        for (int c = 0; c < DH; c++) {
            const float w = W[(h*DH + c)*DD + d];
#pragma unroll
            for (int e = 0; e < DH; e++) acc[e] += w * s_s[c*DH + e];
        }
#pragma unroll
        for (int e = 0; e < DH; e++) {
            float v = acc[e];
            __nv_bfloat16 hi = __float2bfloat16(v);
            float lo = v - __bfloat162float(hi);
            outp[(size_t)(h*DH + e)*2048 + d] = hi;
            outp[(size_t)(h*DH + e)*2048 + 1024 + d] = __float2bfloat16(lo);
        }
    } else {
        const float* __restrict__ W = (z == 2) ? Wv : Wo;
        __nv_bfloat16* __restrict__ outp = (z == 2) ? g_WV2 : g_WO2;
        for (int c = 0; c < DH; c++) {
            const int row = h*DH + c;
            float v = W[(size_t)row*DD + d];
            __nv_bfloat16 hi = __float2bfloat16(v);
            float lo = v - __bfloat162float(hi);
            outp[(size_t)row*2048 + d] = hi;
            outp[(size_t)row*2048 + 1024 + d] = __float2bfloat16(lo);
        }
    }
}

// ---------------------------------------------------------------------------
// fp32 -> bf16 hi/lo split (x only)
// ---------------------------------------------------------------------------
__global__ __launch_bounds__(256)
void cvt_split_kernel(const float* __restrict__ src, __nv_bfloat16* __restrict__ dst, int n)
{
    int i = blockIdx.x * 256 + threadIdx.x;
    if (i >= n) return;
    int r = i >> 10, c = i & 1023;
    float v = src[i];
    __nv_bfloat16 hi = __float2bfloat16(v);
    float lof = v - __bfloat162float(hi);
    dst[(size_t)r*2048 + c] = hi;
    dst[(size_t)r*2048 + 1024 + c] = __float2bfloat16(lof);
}

// ---------------------------------------------------------------------------
// Merged QKV GEMM (QKV=1): grid (24, 32). superblock 0-7->Q, 8-15->K, 16-23->V.
// QKV=0: plain fp32 C (output projection), grid (8, 32).
// ---------------------------------------------------------------------------
#define G2_TILE  (128*144)
#define G2_STAGE (4*G2_TILE)
#define G2_SMEM  (2*G2_STAGE)

template<int QKV>
__global__ __launch_bounds__(256, 1)
void gemm_mma2_kernel(const __nv_bfloat16* __restrict__ A2,
                      const __nv_bfloat16* __restrict__ Bq,
                      const __nv_bfloat16* __restrict__ Bk,
                      const __nv_bfloat16* __restrict__ Bv,
                      float* __restrict__ C, float qscale)
{
    extern __shared__ char smraw[];
    const uint32_t sbase = smem_u32(smraw);
    const int tid = threadIdx.x;
    const int wid = tid >> 5, lane = tid & 31;
    const int warp_m = wid >> 1, warp_n = wid & 1;
    const int m0 = blockIdx.y * 128;
    const int nb = QKV ? (blockIdx.x >> 3) : 0;         // 0=Q,1=K,2=V
    const int n0 = QKV ? ((blockIdx.x & 7) * 128) : (blockIdx.x * 128);
    const __nv_bfloat16* __restrict__ B2 =
        QKV ? ((nb == 0) ? Bq : (nb == 1) ? Bk : Bv) : Bq;

    float acc[2][8][4];
#pragma unroll
    for (int a = 0; a < 2; a++)
#pragma unroll
        for (int b = 0; b < 8; b++)
#pragma unroll
            for (int c = 0; c < 4; c++) acc[a][b][c] = 0.f;

    auto LOAD = [&](int it) {
        const uint32_t st = sbase + (it & 1) * G2_STAGE;
        const char* gAh = (const char*)(A2 + (size_t)m0*2048 + it*64);
        const char* gBh = (const char*)(B2 + (size_t)n0*2048 + it*64);
#pragma unroll
        for (int i = 0; i < 4; i++) {
            int u = tid + i*256;
            int row = u >> 3, kb = (u & 7) << 4;
            const size_t go = (size_t)row*4096 + kb;
            const uint32_t so = row*144 + kb;
            cp_async16(st             + so, gAh + go);
            cp_async16(st +   G2_TILE + so, gAh + 2048 + go);
            cp_async16(st + 2*G2_TILE + so, gBh + go);
            cp_async16(st + 3*G2_TILE + so, gBh + 2048 + go);
        }
    };

    LOAD(0); CP_COMMIT();
    LOAD(1); CP_COMMIT();

    const int NIT = 16;
    for (int it = 0; it < NIT; it++) {
        CP_WAIT1();
        __syncthreads();
        const uint32_t st = sbase + (it & 1) * G2_STAGE;
#pragma unroll
        for (int j = 0; j < 4; j++) {
            const uint32_t cb = j*32 + ((lane >> 4) << 4);
            uint32_t ah[2][4], al[2][4];
#pragma unroll
            for (int mf = 0; mf < 2; mf++) {
                const uint32_t ro = (warp_m*32 + mf*16 + (lane & 15))*144 + cb;
                ldsm4(ah[mf][0], ah[mf][1], ah[mf][2], ah[mf][3], st + ro);
                ldsm4(al[mf][0], al[mf][1], al[mf][2], al[mf][3], st + G2_TILE + ro);
            }
            uint32_t bh[8][2], bl[8][2];
#pragma unroll
            for (int nf2 = 0; nf2 < 4; nf2++) {
                const uint32_t ro = (warp_n*64 + nf2*16 + (lane & 15))*144 + cb;
                uint32_t r0, r1, r2, r3;
                ldsm4(r0, r1, r2, r3, st + 2*G2_TILE + ro);
                bh[nf2*2][0] = r0; bh[nf2*2][1] = r2;
                bh[nf2*2+1][0] = r1; bh[nf2*2+1][1] = r3;
                ldsm4(r0, r1, r2, r3, st + 3*G2_TILE + ro);
                bl[nf2*2][0] = r0; bl[nf2*2][1] = r2;
                bl[nf2*2+1][0] = r1; bl[nf2*2+1][1] = r3;
            }
#pragma unroll
            for (int mf = 0; mf < 2; mf++)
#pragma unroll
                for (int nf = 0; nf < 8; nf++) {
                    mma_bf16(acc[mf][nf], ah[mf], bh[nf]);
                    mma_bf16(acc[mf][nf], ah[mf], bl[nf]);
                    mma_bf16(acc[mf][nf], al[mf], bh[nf]);
                }
        }
        __syncthreads();
        if (it + 2 < NIT) LOAD(it + 2);
        CP_COMMIT();
    }

    const int g = lane >> 2, t = lane & 3;
    if (!QKV || nb < 2) {
#pragma unroll
        for (int mf = 0; mf < 2; mf++) {
            const int row0 = m0 + warp_m*32 + mf*16 + g;
#pragma unroll
            for (int nf = 0; nf < 8; nf++) {
                const int col = n0 + warp_n*64 + nf*8 + t*2;
                if (!QKV) {
                    *(float2*)&C[(size_t)row0*DD + col]     = make_float2(acc[mf][nf][0], acc[mf][nf][1]);
                    *(float2*)&C[(size_t)(row0+8)*DD + col] = make_float2(acc[mf][nf][2], acc[mf][nf][3]);
                } else {
                    __nv_bfloat16* dst = (nb == 0) ? g_Qs : g_Ks;
                    const float sc = (nb == 0) ? qscale : 1.0f;
                    const int h = col >> 6, e = col & 63;
#pragma unroll
                    for (int rr = 0; rr < 2; rr++) {
                        const int row = row0 + rr*8;
                        const int b = row >> 11, tq = row & 2047;
                        const size_t base = ((size_t)(b*HH + h)*TT + tq) << 7;
                        uint32_t hi, lo;
                        split2(acc[mf][nf][rr*2] * sc, acc[mf][nf][rr*2+1] * sc, hi, lo);
                        *(uint32_t*)&dst[base + e]      = hi;
                        *(uint32_t*)&dst[base + 64 + e] = lo;
                    }
                }
            }
        }
    } else {
        // V: transpose through smem -> coalesced f16 stores to g_Vt [bh][d][s]
        __half* sm = (__half*)smraw;            // tile [tq 128][d 128], stride 136 halves
        __syncthreads();
#pragma unroll
        for (int mf = 0; mf < 2; mf++) {
            const int rowl = warp_m*32 + mf*16 + g;
#pragma unroll
            for (int nf = 0; nf < 8; nf++) {
                const int col = warp_n*64 + nf*8 + t*2;
#pragma unroll
                for (int rr = 0; rr < 2; rr++) {
                    __half2 hv = __floats2half2_rn(acc[mf][nf][rr*2], acc[mf][nf][rr*2+1]);
                    *(__half2*)(sm + (size_t)(rowl + rr*8)*136 + col) = hv;
                }
            }
        }
        __syncthreads();
        const int dd = tid >> 1, th = tid & 1;
        const int h = (n0 + dd) >> 6, dl = (n0 + dd) & 63;
        const int b = m0 >> 11;
        const int tq0 = (m0 & 2047) + th*64;
        __half* dst = g_Vt + ((size_t)((b*HH + h)*DH + dl))*TT + tq0;
#pragma unroll
        for (int i8 = 0; i8 < 8; i8++) {
            __half tmp[8];
#pragma unroll
            for (int k = 0; k < 8; k++)
                tmp[k] = sm[(size_t)(th*64 + i8*8 + k)*136 + dd];
            *(uint4*)(dst + i8*8) = *(uint4*)tmp;
        }
    }
}

// ---------------------------------------------------------------------------
// Flash attention on HMMA — 128q / 256thr CTAs, 2 CTAs/SM (104 KB smem via
// XOR swizzle), 64-key chunks, 3-stage pipeline, lazy-max softmax.
// ---------------------------------------------------------------------------
#define AQ_BYTES  (128*256)              // 32768 (swizzled, no pad)
#define AK_ARR    8192                   // 64 rows x 128B
#define A_NST     3
#define A_STAGE   (3*AK_ARR)             // Khi, Klo, V = 24576
#define A_SMEM    (AQ_BYTES + A_NST*A_STAGE)   // 106496

// swizzle: 16B-unit column XOR low-3 bits of row
__device__ __forceinline__ uint32_t swz128(int row, int c8) {       // 128B rows
    return (uint32_t)(row*128 + (((c8 ^ row) & 7) << 4) + ((c8 & ~7) << 4));
}
__device__ __forceinline__ uint32_t swzQ(int row, int c16) {        // 256B rows
    return (uint32_t)(row*256 + ((c16 ^ (row & 7)) << 4) + ((c16 & 8) ? 0 : 0));
}

__global__ __launch_bounds__(256, 2)
void attn_mma_kernel()
{
    extern __shared__ char smraw[];
    const uint32_t sbase = smem_u32(smraw);
    const int tid = threadIdx.x, wid = tid >> 5, lane = tid & 31;
    const int bh = blockIdx.y;
    const int q0 = blockIdx.x * 128;

    const char* Qbase = (const char*)(g_Qs + ((size_t)bh*TT + q0) * 128);
    const char* Kbase = (const char*)(g_Ks + (size_t)bh*TT*128);
    const char* Vbase = (const char*)(g_Vt + (size_t)bh*DH*TT);

    // Q: 128 rows x 256B, swizzled (c16 ^ (row&7) on low 3 bits)
#pragma unroll
    for (int i = 0; i < 8; i++) {
        int u = tid + i*256;                  // 0..2047
        int row = u >> 4, c16 = u & 15;
        uint32_t d = sbase + row*256 + ((((c16 & 7) ^ (row & 7)) | (c16 & 8)) << 4);
        cp_async16(d, Qbase + (size_t)row*256 + (c16 << 4));
    }
    CP_COMMIT();

    auto LOADC = [&](int c) {
        const uint32_t s = sbase + AQ_BYTES + (c % A_NST) * A_STAGE;
        const char* ksrc = Kbase + (size_t)c*64*256;
        const char* vsrc = Vbase + (size_t)c*128;
#pragma unroll
        for (int i = 0; i < 2; i++) {
            int u = tid + i*256;              // 0..511
            int r = u >> 3, c8 = u & 7;
            uint32_t so = (uint32_t)(r*128 + (((c8 ^ r) & 7) << 4));
            cp_async16(s             + so, ksrc + (size_t)r*256 + (c8 << 4));        // Khi
            cp_async16(s +   AK_ARR + so, ksrc + (size_t)r*256 + 128 + (c8 << 4));   // Klo
            cp_async16(s + 2*AK_ARR + so, vsrc + (size_t)r*4096 + (c8 << 4));        // V [d][s]
        }
    };

    LOADC(0); CP_COMMIT();
    LOADC(1); CP_COMMIT();

    CP_WAIT1();               // Q + chunk 0 resident
    __syncthreads();

    // Q hi fragments resident; Q lo reloaded per chunk
    const int qrow = wid*16 + (lane & 15);
    const int qsw = qrow & 7;
    uint32_t qh[4][4];
#pragma unroll
    for (int j = 0; j < 4; j++) {
        int c16 = j*2 + (lane >> 4);
        uint32_t a = sbase + qrow*256 + (((c16 ^ qsw) & 7) << 4) + ((c16 & 8) << 4);
        ldsm4(qh[j][0], qh[j][1], qh[j][2], qh[j][3], a);
    }

    float of[8][4];
#pragma unroll
    for (int f = 0; f < 8; f++)
#pragma unroll
        for (int c4 = 0; c4 < 4; c4++) of[f][c4] = 0.f;
    float m0 = -1e30f, m1 = -1e30f, l0 = 0.f, l1 = 0.f;

    for (int c = 0; c < 32; c++) {
        if (c > 0) { CP_WAIT1(); __syncthreads(); }
        if (c + 2 < 32) LOADC(c + 2);
        CP_COMMIT();

        const uint32_t sK = sbase + AQ_BYTES + (c % A_NST) * A_STAGE;

        // ---- scores (64 keys -> 8 n-fragments) ----
        float sfr[8][4];
#pragma unroll
        for (int f = 0; f < 8; f++)
#pragma unroll
            for (int r4 = 0; r4 < 4; r4++) sfr[f][r4] = 0.f;

#pragma unroll
        for (int j = 0; j < 4; j++) {
            const int kc8 = j*2 + (lane >> 4);
            uint32_t ql[4];
            {
                int c16 = j*2 + (lane >> 4) + 8;   // lo half of Q row
                uint32_t a = sbase + qrow*256 + (((c16 ^ qsw) & 7) << 4) + ((c16 & 8) << 4);
                ldsm4(ql[0], ql[1], ql[2], ql[3], a);
            }
#pragma unroll
            for (int nf2 = 0; nf2 < 4; nf2++) {       // K hi: qh + ql
                const int kr = nf2*16 + (lane & 15);
                uint32_t r0, r1, r2, r3;
                ldsm4(r0, r1, r2, r3, sK + kr*128 + (((kc8 ^ kr) & 7) << 4));
                uint32_t b0[2] = {r0, r2}, b1[2] = {r1, r3};
                mma_bf16(sfr[2*nf2  ], qh[j], b0);
                mma_bf16(sfr[2*nf2  ], ql,    b0);
                mma_bf16(sfr[2*nf2+1], qh[j], b1);
                mma_bf16(sfr[2*nf2+1], ql,    b1);
            }
#pragma unroll
            for (int nf2 = 0; nf2 < 4; nf2++) {       // K lo: qh only
                const int kr = nf2*16 + (lane & 15);
                uint32_t r0, r1, r2, r3;
                ldsm4(r0, r1, r2, r3, sK + AK_ARR + kr*128 + (((kc8 ^ kr) & 7) << 4));
                uint32_t b0[2] = {r0, r2}, b1[2] = {r1, r3};
                mma_bf16(sfr[2*nf2  ], qh[j], b0);
                mma_bf16(sfr[2*nf2+1], qh[j], b1);
            }
        }

        // ---- lazy online softmax (exp2 domain) ----
        float mxl0 = sfr[0][0], mxl1 = sfr[0][2];
#pragma unroll
        for (int f = 0; f < 8; f++) {
            mxl0 = fmaxf(mxl0, fmaxf(sfr[f][0], sfr[f][1]));
            mxl1 = fmaxf(mxl1, fmaxf(sfr[f][2], sfr[f][3]));
        }
        if (__ballot_sync(0xffffffffu, (mxl0 > m0) || (mxl1 > m1))) {
            float mx0 = mxl0, mx1 = mxl1;
            mx0 = fmaxf(mx0, __shfl_xor_sync(0xffffffffu, mx0, 1));
            mx0 = fmaxf(mx0, __shfl_xor_sync(0xffffffffu, mx0, 2));
            mx1 = fmaxf(mx1, __shfl_xor_sync(0xffffffffu, mx1, 1));
            mx1 = fmaxf(mx1, __shfl_xor_sync(0xffffffffu, mx1, 2));
            const float m0n = fmaxf(m0, mx0 + 1.0f);   // +1 margin -> fewer triggers
            const float m1n = fmaxf(m1, mx1 + 1.0f);
            const float corr0 = ex2f(m0 - m0n), corr1 = ex2f(m1 - m1n);
            l0 *= corr0; l1 *= corr1;
#pragma unroll
            for (int f = 0; f < 8; f++) {
                of[f][0] *= corr0; of[f][1] *= corr0;
                of[f][2] *= corr1; of[f][3] *= corr1;
            }
            m0 = m0n; m1 = m1n;
        }

        uint32_t pa[4][4];
        float l0a = 0.f, l1a = 0.f;
#pragma unroll
        for (int f = 0; f < 8; f++) {
            uint32_t p01 = ex2_h2(f2h2u(sfr[f][0] - m0, sfr[f][1] - m0));
            uint32_t p23 = ex2_h2(f2h2u(sfr[f][2] - m1, sfr[f][3] - m1));
            const int j = f >> 1;
            if (f & 1) { pa[j][2] = p01; pa[j][3] = p23; }
            else       { pa[j][0] = p01; pa[j][1] = p23; }
            float2 a = h2u2f2(p01); l0a += a.x + a.y;
            float2 bs = h2u2f2(p23); l1a += bs.x + bs.y;
        }
        l0 += l0a;
        l1 += l1a;

        // ---- PV: single f16 V, 4 k-fragments ----
#pragma unroll
        for (int j = 0; j < 4; j++) {
            const int kc8 = j*2 + (lane >> 4);
#pragma unroll
            for (int nf2 = 0; nf2 < 4; nf2++) {
                const int kr = nf2*16 + (lane & 15);
                uint32_t r0, r1, r2, r3;
                ldsm4(r0, r1, r2, r3, sK + 2*AK_ARR + kr*128 + (((kc8 ^ kr) & 7) << 4));
                uint32_t b0[2] = {r0, r2}, b1[2] = {r1, r3};
                mma_f16(of[2*nf2  ], pa[j], b0);
                mma_f16(of[2*nf2+1], pa[j], b1);
            }
        }
    }

    // epilogue: lane-reduce l, normalize, write split O to g_O2
    l0 += __shfl_xor_sync(0xffffffffu, l0, 1);
    l0 += __shfl_xor_sync(0xffffffffu, l0, 2);
    l1 += __shfl_xor_sync(0xffffffffu, l1, 1);
    l1 += __shfl_xor_sync(0xffffffffu, l1, 2);
    const float inv0 = 1.f / l0, inv1 = 1.f / l1;
    const int b = bh >> 4, h = bh & 15;
    const int g = lane >> 2, t = lane & 3;
    const int qr = q0 + wid*16 + g;
#pragma unroll
    for (int f = 0; f < 8; f++) {
        const int col = h*DH + f*8 + t*2;
#pragma unroll
        for (int rr = 0; rr < 2; rr++) {
            const size_t row = (size_t)(b*TT) + qr + rr*8;
            const float inv = rr ? inv1 : inv0;
            uint32_t hi, lo;
            split2(of[f][rr*2] * inv, of[f][rr*2+1] * inv, hi, lo);
            *(uint32_t*)&g_O2[row*2048 + col]        = hi;
            *(uint32_t*)&g_O2[row*2048 + 1024 + col] = lo;
        }
    }
}

// ---------------------------------------------------------------------------
// Launch. Inputs: 0=x, 1=mask, 2=Wq, 3=Wk, 4=Wv, 5=Wo, 6=S_q, 7=S_k
// Order: weff_all, cvt_x, qkv_gemm, attn (ncu slot), out_gemm.
// ---------------------------------------------------------------------------
extern "C" void kernel_launch(void* const* d_in, const int* in_sizes, int n_in,
                              void* d_out, int out_size)
{
    const float* x  = (const float*)d_in[0];
    const float* Wq = (const float*)d_in[2];
    const float* Wk = (const float*)d_in[3];
    const float* Wv = (const float*)d_in[4];
    const float* Wo = (const float*)d_in[5];
    const float* Sq = (const float*)d_in[6];
    const float* Sk = (const float*)d_in[7];
    float* outp = (float*)d_out;

    __nv_bfloat16 *dA2, *dO2, *dWQ2, *dWK2, *dWV2, *dWO2;
    cudaGetSymbolAddress((void**)&dA2,  g_A2);
    cudaGetSymbolAddress((void**)&dO2,  g_O2);
    cudaGetSymbolAddress((void**)&dWQ2, g_WQ2);
    cudaGetSymbolAddress((void**)&dWK2, g_WK2);
    cudaGetSymbolAddress((void**)&dWV2, g_WV2);
    cudaGetSymbolAddress((void**)&dWO2, g_WO2);

    cudaFuncSetAttribute(gemm_mma2_kernel<0>, cudaFuncAttributeMaxDynamicSharedMemorySize, G2_SMEM);
    cudaFuncSetAttribute(gemm_mma2_kernel<1>, cudaFuncAttributeMaxDynamicSharedMemorySize, G2_SMEM);
    cudaFuncSetAttribute(attn_mma_kernel, cudaFuncAttributeMaxDynamicSharedMemorySize, A_SMEM);

    // 1) weight prep
    weff_all_kernel<<<dim3(DD/256, HH, 4), 256>>>(Wq, Wk, Wv, Wo, Sq, Sk);

    // 2) split x
    cvt_split_kernel<<<(MM*DD)/256, 256>>>(x, dA2, MM*DD);

    // 3) merged QKV projection -> g_Qs, g_Ks, g_Vt
    const float qscale = 0.125f * 1.4426950408889634f;   // scale * log2(e)
    gemm_mma2_kernel<1><<<dim3(24, MM/128), 256, G2_SMEM>>>(dA2, dWQ2, dWK2, dWV2, nullptr, qscale);

    // 4) flash attention -> g_O2   [ncu capture slot]
    attn_mma_kernel<<<dim3(TT/128, BH), 256, A_SMEM>>>();

    // 5) output projection -> d_out fp32
    gemm_mma2_kernel<0><<<dim3(8, MM/128), 256, G2_SMEM>>>(dO2, dWO2, dWO2, dWO2, outp, 1.0f);
}